// round 6
// baseline (speedup 1.0000x reference)
#include <cuda_runtime.h>
#include <math.h>

#define NN 100000
#define EE 800000
#define HALFN 50000
#define NC (NN*64)
#define BNS 0.99999500003749969f  /* 1/sqrt(1+1e-5) */
#define APAD 132
#define WSTR 72                  /* pair-interleaved W stride (words) */
#define OPAD 72
#define MT_WORDS 9216            /* max(64*APAD=8448, 128*OPAD=9216) */
#define NBLK 98                  /* ceil(NN/1024) */

// ---------------- scratch (device globals) ----------------
static __device__ float d_gf[NC];
static __device__ float d_cur[NC];
static __device__ float d_h[NC];
static __device__ float d_acc[NC];
static __device__ float d_u[NC];
static __device__ int   d_ic1[NN], d_ic2[NN];
static __device__ int   d_off1[NN], d_off2[NN];
static __device__ int   d_part[2 * 128];
static __device__ int   d_pofs[2 * 128];
static __device__ int   d_src1[EE], d_dst1[EE], d_src2[EE], d_dst2[EE];
static __device__ int   d_nact[2];

// ---------------- helpers ----------------
__device__ __forceinline__ unsigned f2tf(float x) {
    unsigned r;
    asm("cvt.rna.tf32.f32 %0, %1;" : "=r"(r) : "f"(x));
    return r;
}

__device__ __forceinline__ void mma_tf32(float c[4],
    unsigned a0, unsigned a1, unsigned a2, unsigned a3,
    unsigned b0, unsigned b1)
{
    asm volatile("mma.sync.aligned.m16n8k8.row.col.f32.tf32.tf32.f32 "
        "{%0,%1,%2,%3}, {%4,%5,%6,%7}, {%8,%9}, {%0,%1,%2,%3};\n"
        : "+f"(c[0]), "+f"(c[1]), "+f"(c[2]), "+f"(c[3])
        : "r"(a0), "r"(a1), "r"(a2), "r"(a3), "r"(b0), "r"(b1));
}

__device__ __forceinline__ void red4(float* p, float4 v) {
    asm volatile("red.global.add.v4.f32 [%0], {%1,%2,%3,%4};"
        :: "l"(p), "f"(v.x), "f"(v.y), "f"(v.z), "f"(v.w) : "memory");
}

// W SMEM layout: Wt[n*WSTR + ks + 2*j + b] = W[ks + j + 4*b][n]
// -> thread's (b0,b1) B-fragment is one aligned LDS.64, conflict-free.
__device__ __forceinline__ void load_W_tf32(unsigned* Wt, const float* W, int t) {
#pragma unroll
    for (int s = 0; s < 16; s++) {
        int idx = t + s * 256;
        int n = idx & 63, kslot = idx >> 6;
        int ks = kslot & ~7, rem = kslot & 7;
        int k = ks + (rem >> 1) + 4 * (rem & 1);
        Wt[n * WSTR + kslot] = f2tf(__ldg(W + (size_t)k * 64 + n));
    }
}

// Warp computes rows [e0, e0+16) x 64 cols, K=64.
// At: k-major [64][APAD] tf32. Wt: pair-interleaved layout above.
__device__ __forceinline__ void mma_chunk(const unsigned* At, const unsigned* Wt,
                                          int e0, int lane, float acc[8][4])
{
    int g = lane >> 2, la3 = lane & 3;
    const unsigned* Arow = At + la3 * APAD + e0 + g;
    const unsigned* Brow = Wt + g * WSTR + la3 * 2;
#pragma unroll
    for (int ks = 0; ks < 64; ks += 8) {
        unsigned a0 = Arow[ks * APAD];
        unsigned a1 = Arow[ks * APAD + 8];
        unsigned a2 = Arow[(ks + 4) * APAD];
        unsigned a3 = Arow[(ks + 4) * APAD + 8];
#pragma unroll
        for (int nt = 0; nt < 8; nt++) {
            uint2 b = *(const uint2*)(Brow + nt * 8 * WSTR + ks);
            mma_tf32(acc[nt], a0, a1, a2, a3, b.x, b.y);
        }
    }
}

// ---------------- zero (counts only; d_acc kept zero by finalize invariant) ----------------
__global__ void zero_kernel() {
    int i = blockIdx.x * blockDim.x + threadIdx.x;
    if (i < NN) { d_ic1[i] = 0; d_ic2[i] = 0; }
    if (i < 2)  d_nact[i] = 0;
}

// ---------------- counting sort by dst ----------------
__global__ void count_kernel(const int* __restrict__ ei,
                             const int* __restrict__ delta,
                             const int* __restrict__ selfE) {
    int e = blockIdx.x * blockDim.x + threadIdx.x;
    if (e >= EE) return;
    int d  = ei[EE + e];
    int dl = delta[e];
    int sf = selfE[e];
    if (dl < 1) atomicAdd(&d_ic1[d], 1);
    if ((dl >= 1 && dl < 4) || sf == 1) atomicAdd(&d_ic2[d], 1);
}

__global__ void scan1_kernel() {
    __shared__ int s[1024];
    int m = blockIdx.y;
    const int* ic = m ? d_ic2 : d_ic1;
    int* off = m ? d_off2 : d_off1;
    int tid = threadIdx.x;
    int i = blockIdx.x * 1024 + tid;
    int v = (i < NN) ? ic[i] : 0;
    s[tid] = v; __syncthreads();
#pragma unroll
    for (int o = 1; o < 1024; o <<= 1) {
        int t2 = (tid >= o) ? s[tid - o] : 0;
        __syncthreads();
        s[tid] += t2;
        __syncthreads();
    }
    if (i < NN) off[i] = s[tid] - v;
    if (tid == 1023) d_part[m * 128 + blockIdx.x] = s[1023];
}

__global__ void scan2_kernel() {
    __shared__ int s[128];
    int tid = threadIdx.x;
    for (int m = 0; m < 2; m++) {
        int v = (tid < NBLK) ? d_part[m * 128 + tid] : 0;
        s[tid] = v; __syncthreads();
#pragma unroll
        for (int o = 1; o < 128; o <<= 1) {
            int t2 = (tid >= o) ? s[tid - o] : 0;
            __syncthreads();
            s[tid] += t2;
            __syncthreads();
        }
        d_pofs[m * 128 + tid] = s[tid] - v;
        if (tid == NBLK - 1) d_nact[m] = s[NBLK - 1];
        __syncthreads();
    }
}

__global__ void scan3_kernel() {
    int m = blockIdx.y;
    int* off = m ? d_off2 : d_off1;
    int i = blockIdx.x * 1024 + threadIdx.x;
    if (i < NN) off[i] += d_pofs[m * 128 + blockIdx.x];
}

__global__ void place_kernel(const int* __restrict__ ei,
                             const int* __restrict__ delta,
                             const int* __restrict__ selfE) {
    int e = blockIdx.x * blockDim.x + threadIdx.x;
    if (e >= EE) return;
    int s  = ei[e];
    int d  = ei[EE + e];
    int dl = delta[e];
    int sf = selfE[e];
    if (dl < 1) {
        int pos = atomicAdd(&d_off1[d], 1);
        d_src1[pos] = s; d_dst1[pos] = d;
    }
    if ((dl >= 1 && dl < 4) || sf == 1) {
        int pos = atomicAdd(&d_off2[d], 1);
        d_src2[pos] = s; d_dst2[pos] = d;
    }
}

// ---------------- lin0: gf = relu(bn0(x[:,p,:] @ W + b)) via tf32 mma ----------------
__global__ __launch_bounds__(256) void lin0_kernel(
    const float* __restrict__ x,
    const float* __restrict__ W0a, const float* __restrict__ b0a,
    const float* __restrict__ W0v, const float* __restrict__ b0v,
    const float* __restrict__ bn0g, const float* __restrict__ bn0b)
{
    extern __shared__ unsigned smu[];
    unsigned* At = smu;            // 64*APAD
    unsigned* Wt = smu + 64 * APAD;
    int p = blockIdx.y;
    const float* W    = p ? W0v : W0a;
    const float* bias = p ? b0v : b0a;
    int t = threadIdx.x;
    int hbase = blockIdx.x * 128;
    int warp = t >> 5, lane = t & 31, e0 = warp * 16, g = lane >> 2, la3 = lane & 3;

    float acc[8][4];
#pragma unroll
    for (int i = 0; i < 8; i++)
#pragma unroll
        for (int j = 0; j < 4; j++) acc[i][j] = 0.f;

    for (int kc = 0; kc < 512; kc += 64) {
#pragma unroll
        for (int s = 0; s < 8; s++) {
            int idx = t + s * 256;
            int row = idx & 127, q = idx >> 7;
            int half = hbase + row;
            float4 v = make_float4(0.f, 0.f, 0.f, 0.f);
            if (half < HALFN) {
                int node = half * 2 + p;
                v = __ldg((const float4*)(x + (size_t)node * 1024 + (size_t)p * 512 + kc) + q);
            }
            unsigned* Ap = At + q * 4 * APAD + row;
            Ap[0]        = f2tf(v.x);
            Ap[APAD]     = f2tf(v.y);
            Ap[2 * APAD] = f2tf(v.z);
            Ap[3 * APAD] = f2tf(v.w);
        }
        load_W_tf32(Wt, W + (size_t)kc * 64, t);
        __syncthreads();
        mma_chunk(At, Wt, e0, lane, acc);
        __syncthreads();
    }
    int half1 = hbase + e0 + g, half2 = half1 + 8;
#pragma unroll
    for (int nt = 0; nt < 8; nt++) {
        int c = nt * 8 + 2 * la3;
        float2 bs = __ldg((const float2*)(bias + c));
        float2 gg = __ldg((const float2*)(bn0g + c));
        float2 bb = __ldg((const float2*)(bn0b + c));
        if (half1 < HALFN) {
            int node = half1 * 2 + p;
            float v0 = fmaxf((acc[nt][0] + bs.x) * (BNS * gg.x) + bb.x, 0.f);
            float v1 = fmaxf((acc[nt][1] + bs.y) * (BNS * gg.y) + bb.y, 0.f);
            *(float2*)(d_gf + (size_t)node * 64 + c) = make_float2(v0, v1);
        }
        if (half2 < HALFN) {
            int node = half2 * 2 + p;
            float v2 = fmaxf((acc[nt][2] + bs.x) * (BNS * gg.x) + bb.x, 0.f);
            float v3 = fmaxf((acc[nt][3] + bs.y) * (BNS * gg.y) + bb.y, 0.f);
            *(float2*)(d_gf + (size_t)node * 64 + c) = make_float2(v2, v3);
        }
    }
}

// ---------------- fin_u: fused finalize + u-GEMM ----------------
// mode -1: v = gf[n]                         (no finalize writes)
// mode  0: v = acc/max(cnt1,1)               -> d_h
// mode  1: v = relu(bn(acc/max(cnt2,1)))     -> d_cur
// mode  2: v = relu(bn(acc/cnt2 + cur))      -> d_cur
// then: u = relu(bn1a(v)) @ W1a -> d_u. Re-zeroes d_acc for modes >= 0.
__global__ __launch_bounds__(256) void fin_u_kernel(
    int mode, const float* __restrict__ bng, const float* __restrict__ bnb,
    const float* __restrict__ g1, const float* __restrict__ b1,
    const float* __restrict__ W1a)
{
    extern __shared__ unsigned smu[];
    unsigned* At = smu;
    unsigned* Wt = smu + 64 * APAD;
    int t = threadIdx.x;
    int rbase = blockIdx.x * 128;

    load_W_tf32(Wt, W1a, t);
#pragma unroll
    for (int s = 0; s < 8; s++) {
        int idx = t + s * 256;
        int row = idx & 127, q = idx >> 7;
        int node = rbase + row;
        unsigned* Ap = At + q * 4 * APAD + row;
        if (node < NN) {
            float4 v;
            size_t base = (size_t)node * 64 + q * 4;
            if (mode < 0) {
                v = __ldg((const float4*)(d_gf + base));
            } else {
                const int* cnt = (mode == 0) ? d_ic1 : d_ic2;
                float sc = 1.f / fmaxf((float)cnt[node], 1.f);
                v = *(const float4*)(d_acc + base);
                *(float4*)(d_acc + base) = make_float4(0.f, 0.f, 0.f, 0.f);
                v.x *= sc; v.y *= sc; v.z *= sc; v.w *= sc;
                if (mode >= 2) {
                    float4 r = *(const float4*)(d_cur + base);
                    v.x += r.x; v.y += r.y; v.z += r.z; v.w += r.w;
                }
                if (mode >= 1) {
                    float4 gg = __ldg((const float4*)bng + q);
                    float4 bb = __ldg((const float4*)bnb + q);
                    v.x = fmaxf(v.x * (BNS * gg.x) + bb.x, 0.f);
                    v.y = fmaxf(v.y * (BNS * gg.y) + bb.y, 0.f);
                    v.z = fmaxf(v.z * (BNS * gg.z) + bb.z, 0.f);
                    v.w = fmaxf(v.w * (BNS * gg.w) + bb.w, 0.f);
                }
                float* dst = (mode == 0) ? d_h : d_cur;
                *(float4*)(dst + base) = v;
            }
            float4 sg = __ldg((const float4*)g1 + q);
            float4 sb = __ldg((const float4*)b1 + q);
            Ap[0]        = f2tf(fmaxf(v.x * (BNS * sg.x) + sb.x, 0.f));
            Ap[APAD]     = f2tf(fmaxf(v.y * (BNS * sg.y) + sb.y, 0.f));
            Ap[2 * APAD] = f2tf(fmaxf(v.z * (BNS * sg.z) + sb.z, 0.f));
            Ap[3 * APAD] = f2tf(fmaxf(v.w * (BNS * sg.w) + sb.w, 0.f));
        } else {
            Ap[0] = Ap[APAD] = Ap[2 * APAD] = Ap[3 * APAD] = 0u;
        }
    }
    __syncthreads();

    int warp = t >> 5, lane = t & 31, e0 = warp * 16, g = lane >> 2, la3 = lane & 3;
    float acc[8][4];
#pragma unroll
    for (int i = 0; i < 8; i++)
#pragma unroll
        for (int j = 0; j < 4; j++) acc[i][j] = 0.f;
    mma_chunk(At, Wt, e0, lane, acc);

    int n1 = rbase + e0 + g, n2 = n1 + 8;
#pragma unroll
    for (int nt = 0; nt < 8; nt++) {
        int c = nt * 8 + 2 * la3;
        if (n1 < NN) *(float2*)(d_u + (size_t)n1 * 64 + c) = make_float2(acc[nt][0], acc[nt][1]);
        if (n2 < NN) *(float2*)(d_u + (size_t)n2 * 64 + c) = make_float2(acc[nt][2], acc[nt][3]);
    }
}

// ---------------- EdgeConv message kernel ----------------
__global__ __launch_bounds__(256, 3) void msg_kernel(
    int sel, int maskid,
    const float* __restrict__ g1b, const float* __restrict__ b1b, const float* __restrict__ W1b,
    const float* __restrict__ g2,  const float* __restrict__ b2,  const float* __restrict__ W2)
{
    extern __shared__ unsigned smu[];
    unsigned* Mt  = smu;                     // MT_WORDS (GEMM A / H1 / output tile)
    float*    Ot  = (float*)smu;
    unsigned* Wt1 = smu + MT_WORDS;
    unsigned* Wt2 = Wt1 + 64 * WSTR;
    int* dsts = (int*)(Wt2 + 64 * WSTR);     // 128 ints

    int count = d_nact[maskid];
    int base = blockIdx.x * 128;
    if (base >= count) return;
    const float* xf = (sel == 0) ? d_gf : (sel == 1 ? d_h : d_cur);
    const int* srcL = maskid ? d_src2 : d_src1;
    const int* dstL = maskid ? d_dst2 : d_dst1;
    int t = threadIdx.x;

    load_W_tf32(Wt1, W1b, t);
    load_W_tf32(Wt2, W2, t);
    // gather diff -> bn1b -> relu -> tf32 -> Mt (k-major)
    {
        int e_loc = t & 127, h = t >> 7;
        int e = base + e_loc;
        int act = (e < count);
        int sN = 0, dN = 0;
        if (act) { sN = srcL[e]; dN = dstL[e]; }
        if (h == 0) dsts[e_loc] = act ? dN : -1;
        const float4* xi4 = (const float4*)(xf + (size_t)dN * 64) + h * 8;
        const float4* xj4 = (const float4*)(xf + (size_t)sN * 64) + h * 8;
#pragma unroll
        for (int q = 0; q < 8; q++) {
            float4 a  = __ldg(xi4 + q);
            float4 bv = __ldg(xj4 + q);
            int k = h * 32 + q * 4;
            float4 sg = __ldg((const float4*)g1b + (k >> 2));
            float4 sb = __ldg((const float4*)b1b + (k >> 2));
            unsigned* Mp = Mt + k * APAD + e_loc;
            Mp[0]        = f2tf(fmaxf((bv.x - a.x) * (BNS * sg.x) + sb.x, 0.f));
            Mp[APAD]     = f2tf(fmaxf((bv.y - a.y) * (BNS * sg.y) + sb.y, 0.f));
            Mp[2 * APAD] = f2tf(fmaxf((bv.z - a.z) * (BNS * sg.z) + sb.z, 0.f));
            Mp[3 * APAD] = f2tf(fmaxf((bv.w - a.w) * (BNS * sg.w) + sb.w, 0.f));
        }
    }
    __syncthreads();

    int warp = t >> 5, lane = t & 31, e0 = warp * 16, g = lane >> 2, la3 = lane & 3;
    float acc[8][4];
#pragma unroll
    for (int i = 0; i < 8; i++)
#pragma unroll
        for (int j = 0; j < 4; j++) acc[i][j] = 0.f;
    mma_chunk(Mt, Wt1, e0, lane, acc);

    // epilogue1: H1 = relu(bn2(acc + u[dst])) -> back into Mt (own e-columns only)
    int d1 = dsts[e0 + g], d2 = dsts[e0 + g + 8];
#pragma unroll
    for (int nt = 0; nt < 8; nt++) {
        int c = nt * 8 + 2 * la3;
        float2 gg = __ldg((const float2*)(g2 + c));
        float2 bb = __ldg((const float2*)(b2 + c));
        float u0 = 0.f, u1 = 0.f, u2 = 0.f, u3 = 0.f;
        if (d1 >= 0) { float2 u = __ldg((const float2*)(d_u + (size_t)d1 * 64 + c)); u0 = u.x; u1 = u.y; }
        if (d2 >= 0) { float2 u = __ldg((const float2*)(d_u + (size_t)d2 * 64 + c)); u2 = u.x; u3 = u.y; }
        float h00 = fmaxf((acc[nt][0] + u0) * (BNS * gg.x) + bb.x, 0.f);
        float h01 = fmaxf((acc[nt][1] + u1) * (BNS * gg.y) + bb.y, 0.f);
        float h10 = fmaxf((acc[nt][2] + u2) * (BNS * gg.x) + bb.x, 0.f);
        float h11 = fmaxf((acc[nt][3] + u3) * (BNS * gg.y) + bb.y, 0.f);
        Mt[c * APAD + e0 + g]           = f2tf(h00);
        Mt[(c + 1) * APAD + e0 + g]     = f2tf(h01);
        Mt[c * APAD + e0 + g + 8]       = f2tf(h10);
        Mt[(c + 1) * APAD + e0 + g + 8] = f2tf(h11);
    }
    __syncwarp();

    float acc2[8][4];
#pragma unroll
    for (int i = 0; i < 8; i++)
#pragma unroll
        for (int j = 0; j < 4; j++) acc2[i][j] = 0.f;
    mma_chunk(Mt, Wt2, e0, lane, acc2);

    __syncthreads();
#pragma unroll
    for (int nt = 0; nt < 8; nt++) {
        int c = nt * 8 + 2 * la3;
        *(float2*)(Ot + (e0 + g) * OPAD + c)     = make_float2(acc2[nt][0], acc2[nt][1]);
        *(float2*)(Ot + (e0 + g + 8) * OPAD + c) = make_float2(acc2[nt][2], acc2[nt][3]);
    }
    __syncthreads();

    // segmented reduction over sorted dsts: one red.v4 per (segment, 4-col chunk)
    {
        int cc = t & 15;
        int rg = t >> 4;
        float4 sum = make_float4(0.f, 0.f, 0.f, 0.f);
        int cur = -1;
#pragma unroll
        for (int i = 0; i < 8; i++) {
            int r = rg * 8 + i;
            int dd = dsts[r];
            float4 v = *(const float4*)(Ot + r * OPAD + cc * 4);
            if (dd != cur) {
                if (cur >= 0) red4(d_acc + (size_t)cur * 64 + cc * 4, sum);
                cur = dd;
                sum = v;
            } else {
                sum.x += v.x; sum.y += v.y; sum.z += v.z; sum.w += v.w;
            }
        }
        if (cur >= 0) red4(d_acc + (size_t)cur * 64 + cc * 4, sum);
    }
}

// ---------------- finalize (last stage only): cur = acc/cnt2 + cur, re-zero acc ----------------
__global__ void finalize3_kernel() {
    int i = blockIdx.x * blockDim.x + threadIdx.x;
    if (i >= NC) return;
    int n = i >> 6;
    float v = d_acc[i] / fmaxf((float)d_ic2[n], 1.f);
    d_acc[i] = 0.f;
    d_cur[i] = v + d_cur[i];
}

// ---------------- heads ----------------
__global__ void heads_kernel(const float* __restrict__ fcW, const float* __restrict__ fcb,
                             const float* __restrict__ fcaW, const float* __restrict__ fcab,
                             const float* __restrict__ fcvW, const float* __restrict__ fcvb,
                             float* __restrict__ out)
{
    int n = blockIdx.x * blockDim.x + threadIdx.x;
    if (n >= NN) return;
    const float* f = d_cur + (size_t)n * 64;
    const float* g = d_gf  + (size_t)n * 64;
    bool even = (n & 1) == 0;
    const float* hw = even ? fcaW : fcvW;
    const float* hb = even ? fcab : fcvb;
    float o0 = fcb[0], o1 = fcb[1], h0 = hb[0], h1 = hb[1];
#pragma unroll 8
    for (int c = 0; c < 64; ++c) {
        float fv = f[c], gv = g[c];
        o0 += fv * fcW[2 * c];  o1 += fv * fcW[2 * c + 1];
        h0 += gv * hw[2 * c];   h1 += gv * hw[2 * c + 1];
    }
    out[2 * n] = o0; out[2 * n + 1] = o1;
    size_t off = even ? (size_t)2 * NN + (size_t)(n >> 1) * 2
                      : (size_t)2 * NN + (size_t)2 * HALFN + (size_t)(n >> 1) * 2;
    out[off] = h0; out[off + 1] = h1;
}

// ---------------- launch ----------------
extern "C" void kernel_launch(void* const* d_in, const int* in_sizes, int n_in,
                              void* d_out, int out_size) {
    const float* x    = (const float*)d_in[0];
    const int*   ei   = (const int*)d_in[1];
    const int*   dl   = (const int*)d_in[2];
    const int*   se   = (const int*)d_in[3];
    const float* W0a  = (const float*)d_in[5];
    const float* b0a  = (const float*)d_in[6];
    const float* W0v  = (const float*)d_in[7];
    const float* b0v  = (const float*)d_in[8];
    const float* bn0g = (const float*)d_in[9];
    const float* bn0b = (const float*)d_in[10];
    const float* ec1g = (const float*)d_in[11];
    const float* ec1b = (const float*)d_in[12];
    const float* ecW1 = (const float*)d_in[13];
    const float* ec2g = (const float*)d_in[14];
    const float* ec2b = (const float*)d_in[15];
    const float* ecW2 = (const float*)d_in[16];
    const float* bng  = (const float*)d_in[17];
    const float* bnb  = (const float*)d_in[18];
    const float* fcaW = (const float*)d_in[19];
    const float* fcab = (const float*)d_in[20];
    const float* fcvW = (const float*)d_in[21];
    const float* fcvb = (const float*)d_in[22];
    const float* fcW  = (const float*)d_in[23];
    const float* fcb  = (const float*)d_in[24];
    float* out = (float*)d_out;

    const int GEMM_SMEM = (64 * APAD + 64 * WSTR) * 4;                 // 52224
    const int MSG_SMEM  = (MT_WORDS + 2 * 64 * WSTR + 128) * 4;        // 74240
    cudaFuncSetAttribute(msg_kernel,   cudaFuncAttributeMaxDynamicSharedMemorySize, MSG_SMEM);
    cudaFuncSetAttribute(lin0_kernel,  cudaFuncAttributeMaxDynamicSharedMemorySize, GEMM_SMEM);
    cudaFuncSetAttribute(fin_u_kernel, cudaFuncAttributeMaxDynamicSharedMemorySize, GEMM_SMEM);

    zero_kernel<<<(NN + 255) / 256, 256>>>();
    count_kernel<<<EE / 256, 256>>>(ei, dl, se);
    scan1_kernel<<<dim3(NBLK, 2), 1024>>>();
    scan2_kernel<<<1, 128>>>();
    scan3_kernel<<<dim3(NBLK, 2), 1024>>>();
    place_kernel<<<EE / 256, 256>>>(ei, dl, se);
    lin0_kernel<<<dim3((HALFN + 127) / 128, 2), 256, GEMM_SMEM>>>(x, W0a, b0a, W0v, b0v, bn0g, bn0b);

    int msgGrid = (EE + 127) / 128;
    int nuGrid  = (NN + 127) / 128;
    int finGrid = (NC + 255) / 256;

    // u for k=0 mask1 (features = gf)
    fin_u_kernel<<<nuGrid, 256, GEMM_SMEM>>>(-1, nullptr, nullptr, ec1g, ec1b, ecW1);

    for (int k = 0; k < 4; ++k) {
        const float* g1  = ec1g + k * 128;
        const float* b1  = ec1b + k * 128;
        const float* W1  = ecW1 + k * 8192;
        const float* g2  = ec2g + k * 64;
        const float* b2  = ec2b + k * 64;
        const float* W2  = ecW2 + k * 4096;
        int sel_cur = (k == 0) ? 0 : 2;

        msg_kernel<<<msgGrid, 256, MSG_SMEM>>>(sel_cur, 0, g1 + 64, b1 + 64, W1 + 4096, g2, b2, W2);
        // finalize(mask1 mean -> d_h) + u for mask2 (same block weights)
        fin_u_kernel<<<nuGrid, 256, GEMM_SMEM>>>(0, nullptr, nullptr, g1, b1, W1);
        msg_kernel<<<msgGrid, 256, MSG_SMEM>>>(1, 1, g1 + 64, b1 + 64, W1 + 4096, g2, b2, W2);
        if (k < 3) {
            // finalize(mask2 -> d_cur with bn/relu/residual) + u for next block's mask1
            int mode = (k == 0) ? 1 : 2;
            fin_u_kernel<<<nuGrid, 256, GEMM_SMEM>>>(mode, bng + k * 64, bnb + k * 64,
                ec1g + (k + 1) * 128, ec1b + (k + 1) * 128, ecW1 + (k + 1) * 8192);
        } else {
            finalize3_kernel<<<finGrid, 256>>>();
        }
    }
    heads_kernel<<<(NN + 255) / 256, 256>>>(fcW, fcb, fcaW, fcab, fcvW, fcvb, out);
}

// round 7
// speedup vs baseline: 1.0113x; 1.0113x over previous
#include <cuda_runtime.h>
#include <math.h>

#define NN 100000
#define EE 800000
#define HALFN 50000
#define NC (NN*64)
#define BNS 0.99999500003749969f  /* 1/sqrt(1+1e-5) */
#define APAD 132
#define WSTR 72                  /* pair-interleaved W stride (words) */
#define OPAD 72
#define MT_WORDS 9216            /* max(64*APAD=8448, 128*OPAD=9216) */
#define NBLK 98                  /* ceil(NN/1024) */
#define MSG_GRID 444             /* 148 SMs x 3 resident blocks */

// ---------------- scratch (device globals) ----------------
static __device__ float d_gf[NC];
static __device__ float d_cur[NC];
static __device__ float d_h[NC];
static __device__ float d_acc[NC];
static __device__ float d_u[NC];
static __device__ int   d_ic1[NN], d_ic2[NN];
static __device__ int   d_off1[NN], d_off2[NN];
static __device__ int   d_part[2 * 128];
static __device__ int   d_pofs[2 * 128];
static __device__ int   d_src1[EE], d_dst1[EE], d_src2[EE], d_dst2[EE];
static __device__ int   d_nact[2];

// ---------------- helpers ----------------
__device__ __forceinline__ unsigned f2tf(float x) {
    unsigned r;
    asm("cvt.rna.tf32.f32 %0, %1;" : "=r"(r) : "f"(x));
    return r;
}

__device__ __forceinline__ void mma_tf32(float c[4],
    unsigned a0, unsigned a1, unsigned a2, unsigned a3,
    unsigned b0, unsigned b1)
{
    asm volatile("mma.sync.aligned.m16n8k8.row.col.f32.tf32.tf32.f32 "
        "{%0,%1,%2,%3}, {%4,%5,%6,%7}, {%8,%9}, {%0,%1,%2,%3};\n"
        : "+f"(c[0]), "+f"(c[1]), "+f"(c[2]), "+f"(c[3])
        : "r"(a0), "r"(a1), "r"(a2), "r"(a3), "r"(b0), "r"(b1));
}

__device__ __forceinline__ void red4(float* p, float4 v) {
    asm volatile("red.global.add.v4.f32 [%0], {%1,%2,%3,%4};"
        :: "l"(p), "f"(v.x), "f"(v.y), "f"(v.z), "f"(v.w) : "memory");
}

// W SMEM layout: Wt[n*WSTR + ks + 2*j + b] = W[ks + j + 4*b][n]
// -> thread's (b0,b1) B-fragment is one aligned LDS.64, conflict-free.
__device__ __forceinline__ void load_W_tf32(unsigned* Wt, const float* W, int t) {
#pragma unroll
    for (int s = 0; s < 16; s++) {
        int idx = t + s * 256;
        int n = idx & 63, kslot = idx >> 6;
        int ks = kslot & ~7, rem = kslot & 7;
        int k = ks + (rem >> 1) + 4 * (rem & 1);
        Wt[n * WSTR + kslot] = f2tf(__ldg(W + (size_t)k * 64 + n));
    }
}

// Warp computes rows [e0, e0+16) x 64 cols, K=64.
__device__ __forceinline__ void mma_chunk(const unsigned* At, const unsigned* Wt,
                                          int e0, int lane, float acc[8][4])
{
    int g = lane >> 2, la3 = lane & 3;
    const unsigned* Arow = At + la3 * APAD + e0 + g;
    const unsigned* Brow = Wt + g * WSTR + la3 * 2;
#pragma unroll
    for (int ks = 0; ks < 64; ks += 8) {
        unsigned a0 = Arow[ks * APAD];
        unsigned a1 = Arow[ks * APAD + 8];
        unsigned a2 = Arow[(ks + 4) * APAD];
        unsigned a3 = Arow[(ks + 4) * APAD + 8];
#pragma unroll
        for (int nt = 0; nt < 8; nt++) {
            uint2 b = *(const uint2*)(Brow + nt * 8 * WSTR + ks);
            mma_tf32(acc[nt], a0, a1, a2, a3, b.x, b.y);
        }
    }
}

// ---------------- zero (counts only; d_acc kept zero by finalize invariant) ----------------
__global__ void zero_kernel() {
    int i = blockIdx.x * blockDim.x + threadIdx.x;
    if (i < NN) { d_ic1[i] = 0; d_ic2[i] = 0; }
    if (i < 2)  d_nact[i] = 0;
}

// ---------------- counting sort by dst ----------------
__global__ void count_kernel(const int* __restrict__ ei,
                             const int* __restrict__ delta,
                             const int* __restrict__ selfE) {
    int e = blockIdx.x * blockDim.x + threadIdx.x;
    if (e >= EE) return;
    int d  = ei[EE + e];
    int dl = delta[e];
    int sf = selfE[e];
    if (dl < 1) atomicAdd(&d_ic1[d], 1);
    if ((dl >= 1 && dl < 4) || sf == 1) atomicAdd(&d_ic2[d], 1);
}

__global__ void scan1_kernel() {
    __shared__ int s[1024];
    int m = blockIdx.y;
    const int* ic = m ? d_ic2 : d_ic1;
    int* off = m ? d_off2 : d_off1;
    int tid = threadIdx.x;
    int i = blockIdx.x * 1024 + tid;
    int v = (i < NN) ? ic[i] : 0;
    s[tid] = v; __syncthreads();
#pragma unroll
    for (int o = 1; o < 1024; o <<= 1) {
        int t2 = (tid >= o) ? s[tid - o] : 0;
        __syncthreads();
        s[tid] += t2;
        __syncthreads();
    }
    if (i < NN) off[i] = s[tid] - v;
    if (tid == 1023) d_part[m * 128 + blockIdx.x] = s[1023];
}

__global__ void scan2_kernel() {
    __shared__ int s[128];
    int tid = threadIdx.x;
    for (int m = 0; m < 2; m++) {
        int v = (tid < NBLK) ? d_part[m * 128 + tid] : 0;
        s[tid] = v; __syncthreads();
#pragma unroll
        for (int o = 1; o < 128; o <<= 1) {
            int t2 = (tid >= o) ? s[tid - o] : 0;
            __syncthreads();
            s[tid] += t2;
            __syncthreads();
        }
        d_pofs[m * 128 + tid] = s[tid] - v;
        if (tid == NBLK - 1) d_nact[m] = s[NBLK - 1];
        __syncthreads();
    }
}

__global__ void scan3_kernel() {
    int m = blockIdx.y;
    int* off = m ? d_off2 : d_off1;
    int i = blockIdx.x * 1024 + threadIdx.x;
    if (i < NN) off[i] += d_pofs[m * 128 + blockIdx.x];
}

__global__ void place_kernel(const int* __restrict__ ei,
                             const int* __restrict__ delta,
                             const int* __restrict__ selfE) {
    int e = blockIdx.x * blockDim.x + threadIdx.x;
    if (e >= EE) return;
    int s  = ei[e];
    int d  = ei[EE + e];
    int dl = delta[e];
    int sf = selfE[e];
    if (dl < 1) {
        int pos = atomicAdd(&d_off1[d], 1);
        d_src1[pos] = s; d_dst1[pos] = d;
    }
    if ((dl >= 1 && dl < 4) || sf == 1) {
        int pos = atomicAdd(&d_off2[d], 1);
        d_src2[pos] = s; d_dst2[pos] = d;
    }
}

// ---------------- lin0: gf = relu(bn0(x[:,p,:] @ W + b)) via tf32 mma ----------------
__global__ __launch_bounds__(256) void lin0_kernel(
    const float* __restrict__ x,
    const float* __restrict__ W0a, const float* __restrict__ b0a,
    const float* __restrict__ W0v, const float* __restrict__ b0v,
    const float* __restrict__ bn0g, const float* __restrict__ bn0b)
{
    extern __shared__ unsigned smu[];
    unsigned* At = smu;            // 64*APAD
    unsigned* Wt = smu + 64 * APAD;
    int p = blockIdx.y;
    const float* W    = p ? W0v : W0a;
    const float* bias = p ? b0v : b0a;
    int t = threadIdx.x;
    int hbase = blockIdx.x * 128;
    int warp = t >> 5, lane = t & 31, e0 = warp * 16, g = lane >> 2, la3 = lane & 3;

    float acc[8][4];
#pragma unroll
    for (int i = 0; i < 8; i++)
#pragma unroll
        for (int j = 0; j < 4; j++) acc[i][j] = 0.f;

    for (int kc = 0; kc < 512; kc += 64) {
#pragma unroll
        for (int s = 0; s < 8; s++) {
            int idx = t + s * 256;
            int row = idx & 127, q = idx >> 7;
            int half = hbase + row;
            float4 v = make_float4(0.f, 0.f, 0.f, 0.f);
            if (half < HALFN) {
                int node = half * 2 + p;
                v = __ldg((const float4*)(x + (size_t)node * 1024 + (size_t)p * 512 + kc) + q);
            }
            unsigned* Ap = At + q * 4 * APAD + row;
            Ap[0]        = f2tf(v.x);
            Ap[APAD]     = f2tf(v.y);
            Ap[2 * APAD] = f2tf(v.z);
            Ap[3 * APAD] = f2tf(v.w);
        }
        load_W_tf32(Wt, W + (size_t)kc * 64, t);
        __syncthreads();
        mma_chunk(At, Wt, e0, lane, acc);
        __syncthreads();
    }
    int half1 = hbase + e0 + g, half2 = half1 + 8;
#pragma unroll
    for (int nt = 0; nt < 8; nt++) {
        int c = nt * 8 + 2 * la3;
        float2 bs = __ldg((const float2*)(bias + c));
        float2 gg = __ldg((const float2*)(bn0g + c));
        float2 bb = __ldg((const float2*)(bn0b + c));
        if (half1 < HALFN) {
            int node = half1 * 2 + p;
            float v0 = fmaxf((acc[nt][0] + bs.x) * (BNS * gg.x) + bb.x, 0.f);
            float v1 = fmaxf((acc[nt][1] + bs.y) * (BNS * gg.y) + bb.y, 0.f);
            *(float2*)(d_gf + (size_t)node * 64 + c) = make_float2(v0, v1);
        }
        if (half2 < HALFN) {
            int node = half2 * 2 + p;
            float v2 = fmaxf((acc[nt][2] + bs.x) * (BNS * gg.x) + bb.x, 0.f);
            float v3 = fmaxf((acc[nt][3] + bs.y) * (BNS * gg.y) + bb.y, 0.f);
            *(float2*)(d_gf + (size_t)node * 64 + c) = make_float2(v2, v3);
        }
    }
}

// ---------------- fin_u: fused finalize + u-GEMM ----------------
// mode -1: v = gf[n]; mode 0: v=acc/cnt1 -> d_h; mode 1: relu(bn(acc/cnt2)) -> d_cur;
// mode 2: relu(bn(acc/cnt2 + cur)) -> d_cur. Then u = relu(bn1a(v)) @ W1a -> d_u.
__global__ __launch_bounds__(256) void fin_u_kernel(
    int mode, const float* __restrict__ bng, const float* __restrict__ bnb,
    const float* __restrict__ g1, const float* __restrict__ b1,
    const float* __restrict__ W1a)
{
    extern __shared__ unsigned smu[];
    unsigned* At = smu;
    unsigned* Wt = smu + 64 * APAD;
    int t = threadIdx.x;
    int rbase = blockIdx.x * 128;

    load_W_tf32(Wt, W1a, t);
#pragma unroll
    for (int s = 0; s < 8; s++) {
        int idx = t + s * 256;
        int row = idx & 127, q = idx >> 7;
        int node = rbase + row;
        unsigned* Ap = At + q * 4 * APAD + row;
        if (node < NN) {
            float4 v;
            size_t base = (size_t)node * 64 + q * 4;
            if (mode < 0) {
                v = __ldg((const float4*)(d_gf + base));
            } else {
                const int* cnt = (mode == 0) ? d_ic1 : d_ic2;
                float sc = 1.f / fmaxf((float)cnt[node], 1.f);
                v = *(const float4*)(d_acc + base);
                *(float4*)(d_acc + base) = make_float4(0.f, 0.f, 0.f, 0.f);
                v.x *= sc; v.y *= sc; v.z *= sc; v.w *= sc;
                if (mode >= 2) {
                    float4 r = *(const float4*)(d_cur + base);
                    v.x += r.x; v.y += r.y; v.z += r.z; v.w += r.w;
                }
                if (mode >= 1) {
                    float4 gg = __ldg((const float4*)bng + q);
                    float4 bb = __ldg((const float4*)bnb + q);
                    v.x = fmaxf(v.x * (BNS * gg.x) + bb.x, 0.f);
                    v.y = fmaxf(v.y * (BNS * gg.y) + bb.y, 0.f);
                    v.z = fmaxf(v.z * (BNS * gg.z) + bb.z, 0.f);
                    v.w = fmaxf(v.w * (BNS * gg.w) + bb.w, 0.f);
                }
                float* dst = (mode == 0) ? d_h : d_cur;
                *(float4*)(dst + base) = v;
            }
            float4 sg = __ldg((const float4*)g1 + q);
            float4 sb = __ldg((const float4*)b1 + q);
            Ap[0]        = f2tf(fmaxf(v.x * (BNS * sg.x) + sb.x, 0.f));
            Ap[APAD]     = f2tf(fmaxf(v.y * (BNS * sg.y) + sb.y, 0.f));
            Ap[2 * APAD] = f2tf(fmaxf(v.z * (BNS * sg.z) + sb.z, 0.f));
            Ap[3 * APAD] = f2tf(fmaxf(v.w * (BNS * sg.w) + sb.w, 0.f));
        } else {
            Ap[0] = Ap[APAD] = Ap[2 * APAD] = Ap[3 * APAD] = 0u;
        }
    }
    __syncthreads();

    int warp = t >> 5, lane = t & 31, e0 = warp * 16, g = lane >> 2, la3 = lane & 3;
    float acc[8][4];
#pragma unroll
    for (int i = 0; i < 8; i++)
#pragma unroll
        for (int j = 0; j < 4; j++) acc[i][j] = 0.f;
    mma_chunk(At, Wt, e0, lane, acc);

    int n1 = rbase + e0 + g, n2 = n1 + 8;
#pragma unroll
    for (int nt = 0; nt < 8; nt++) {
        int c = nt * 8 + 2 * la3;
        if (n1 < NN) *(float2*)(d_u + (size_t)n1 * 64 + c) = make_float2(acc[nt][0], acc[nt][1]);
        if (n2 < NN) *(float2*)(d_u + (size_t)n2 * 64 + c) = make_float2(acc[nt][2], acc[nt][3]);
    }
}

// ---------------- EdgeConv message kernel (persistent blocks) ----------------
__global__ __launch_bounds__(256, 3) void msg_kernel(
    int sel, int maskid,
    const float* __restrict__ g1b, const float* __restrict__ b1b, const float* __restrict__ W1b,
    const float* __restrict__ g2,  const float* __restrict__ b2,  const float* __restrict__ W2)
{
    extern __shared__ unsigned smu[];
    unsigned* Mt  = smu;                     // MT_WORDS (GEMM A / H1 / output tile)
    float*    Ot  = (float*)smu;
    unsigned* Wt1 = smu + MT_WORDS;
    unsigned* Wt2 = Wt1 + 64 * WSTR;
    int* dsts = (int*)(Wt2 + 64 * WSTR);     // 128 ints

    int count = d_nact[maskid];
    if (blockIdx.x * 128 >= count) return;   // uniform per block
    const float* xf = (sel == 0) ? d_gf : (sel == 1 ? d_h : d_cur);
    const int* srcL = maskid ? d_src2 : d_src1;
    const int* dstL = maskid ? d_dst2 : d_dst1;
    int t = threadIdx.x;
    int warp = t >> 5, lane = t & 31, e0 = warp * 16, g = lane >> 2, la3 = lane & 3;
    int e_loc = t & 127, h = t >> 7;

    // weights loaded ONCE per persistent block
    load_W_tf32(Wt1, W1b, t);
    load_W_tf32(Wt2, W2, t);

    for (int tile = blockIdx.x; tile * 128 < count; tile += gridDim.x) {
        int base = tile * 128;
        // gather diff -> bn1b -> relu -> tf32 -> Mt (k-major)
        {
            int e = base + e_loc;
            int act = (e < count);
            int sN = 0, dN = 0;
            if (act) { sN = srcL[e]; dN = dstL[e]; }
            if (h == 0) dsts[e_loc] = act ? dN : -1;
            const float4* xi4 = (const float4*)(xf + (size_t)dN * 64) + h * 8;
            const float4* xj4 = (const float4*)(xf + (size_t)sN * 64) + h * 8;
#pragma unroll
            for (int q = 0; q < 8; q++) {
                float4 a  = __ldg(xi4 + q);
                float4 bv = __ldg(xj4 + q);
                int k = h * 32 + q * 4;
                float4 sg = __ldg((const float4*)g1b + (k >> 2));
                float4 sb = __ldg((const float4*)b1b + (k >> 2));
                unsigned* Mp = Mt + k * APAD + e_loc;
                Mp[0]        = f2tf(fmaxf((bv.x - a.x) * (BNS * sg.x) + sb.x, 0.f));
                Mp[APAD]     = f2tf(fmaxf((bv.y - a.y) * (BNS * sg.y) + sb.y, 0.f));
                Mp[2 * APAD] = f2tf(fmaxf((bv.z - a.z) * (BNS * sg.z) + sb.z, 0.f));
                Mp[3 * APAD] = f2tf(fmaxf((bv.w - a.w) * (BNS * sg.w) + sb.w, 0.f));
            }
        }
        __syncthreads();

        float acc[8][4];
#pragma unroll
        for (int i = 0; i < 8; i++)
#pragma unroll
            for (int j = 0; j < 4; j++) acc[i][j] = 0.f;
        mma_chunk(Mt, Wt1, e0, lane, acc);

        // epilogue1: H1 = relu(bn2(acc + u[dst])) -> back into Mt (own e-columns only)
        int d1 = dsts[e0 + g], d2 = dsts[e0 + g + 8];
#pragma unroll
        for (int nt = 0; nt < 8; nt++) {
            int c = nt * 8 + 2 * la3;
            float2 gg = __ldg((const float2*)(g2 + c));
            float2 bb = __ldg((const float2*)(b2 + c));
            float u0 = 0.f, u1 = 0.f, u2 = 0.f, u3 = 0.f;
            if (d1 >= 0) { float2 u = __ldg((const float2*)(d_u + (size_t)d1 * 64 + c)); u0 = u.x; u1 = u.y; }
            if (d2 >= 0) { float2 u = __ldg((const float2*)(d_u + (size_t)d2 * 64 + c)); u2 = u.x; u3 = u.y; }
            float h00 = fmaxf((acc[nt][0] + u0) * (BNS * gg.x) + bb.x, 0.f);
            float h01 = fmaxf((acc[nt][1] + u1) * (BNS * gg.y) + bb.y, 0.f);
            float h10 = fmaxf((acc[nt][2] + u2) * (BNS * gg.x) + bb.x, 0.f);
            float h11 = fmaxf((acc[nt][3] + u3) * (BNS * gg.y) + bb.y, 0.f);
            Mt[c * APAD + e0 + g]           = f2tf(h00);
            Mt[(c + 1) * APAD + e0 + g]     = f2tf(h01);
            Mt[c * APAD + e0 + g + 8]       = f2tf(h10);
            Mt[(c + 1) * APAD + e0 + g + 8] = f2tf(h11);
        }
        __syncwarp();

        float acc2[8][4];
#pragma unroll
        for (int i = 0; i < 8; i++)
#pragma unroll
            for (int j = 0; j < 4; j++) acc2[i][j] = 0.f;
        mma_chunk(Mt, Wt2, e0, lane, acc2);

        __syncthreads();
#pragma unroll
        for (int nt = 0; nt < 8; nt++) {
            int c = nt * 8 + 2 * la3;
            *(float2*)(Ot + (e0 + g) * OPAD + c)     = make_float2(acc2[nt][0], acc2[nt][1]);
            *(float2*)(Ot + (e0 + g + 8) * OPAD + c) = make_float2(acc2[nt][2], acc2[nt][3]);
        }
        __syncthreads();

        // segmented reduction over sorted dsts: one red.v4 per (segment, 4-col chunk)
        {
            int cc = t & 15;
            int rg = t >> 4;
            float4 sum = make_float4(0.f, 0.f, 0.f, 0.f);
            int cur = -1;
#pragma unroll
            for (int i = 0; i < 8; i++) {
                int r = rg * 8 + i;
                int dd = dsts[r];
                float4 v = *(const float4*)(Ot + r * OPAD + cc * 4);
                if (dd != cur) {
                    if (cur >= 0) red4(d_acc + (size_t)cur * 64 + cc * 4, sum);
                    cur = dd;
                    sum = v;
                } else {
                    sum.x += v.x; sum.y += v.y; sum.z += v.z; sum.w += v.w;
                }
            }
            if (cur >= 0) red4(d_acc + (size_t)cur * 64 + cc * 4, sum);
        }
        __syncthreads();   // protect Mt/Ot reuse by next tile
    }
}

// ---------------- finalize (last stage only): cur = acc/cnt2 + cur, re-zero acc ----------------
__global__ void finalize3_kernel() {
    int i = blockIdx.x * blockDim.x + threadIdx.x;
    if (i >= NC) return;
    int n = i >> 6;
    float v = d_acc[i] / fmaxf((float)d_ic2[n], 1.f);
    d_acc[i] = 0.f;
    d_cur[i] = v + d_cur[i];
}

// ---------------- heads ----------------
__global__ void heads_kernel(const float* __restrict__ fcW, const float* __restrict__ fcb,
                             const float* __restrict__ fcaW, const float* __restrict__ fcab,
                             const float* __restrict__ fcvW, const float* __restrict__ fcvb,
                             float* __restrict__ out)
{
    int n = blockIdx.x * blockDim.x + threadIdx.x;
    if (n >= NN) return;
    const float* f = d_cur + (size_t)n * 64;
    const float* g = d_gf  + (size_t)n * 64;
    bool even = (n & 1) == 0;
    const float* hw = even ? fcaW : fcvW;
    const float* hb = even ? fcab : fcvb;
    float o0 = fcb[0], o1 = fcb[1], h0 = hb[0], h1 = hb[1];
#pragma unroll 8
    for (int c = 0; c < 64; ++c) {
        float fv = f[c], gv = g[c];
        o0 += fv * fcW[2 * c];  o1 += fv * fcW[2 * c + 1];
        h0 += gv * hw[2 * c];   h1 += gv * hw[2 * c + 1];
    }
    out[2 * n] = o0; out[2 * n + 1] = o1;
    size_t off = even ? (size_t)2 * NN + (size_t)(n >> 1) * 2
                      : (size_t)2 * NN + (size_t)2 * HALFN + (size_t)(n >> 1) * 2;
    out[off] = h0; out[off + 1] = h1;
}

// ---------------- launch ----------------
extern "C" void kernel_launch(void* const* d_in, const int* in_sizes, int n_in,
                              void* d_out, int out_size) {
    const float* x    = (const float*)d_in[0];
    const int*   ei   = (const int*)d_in[1];
    const int*   dl   = (const int*)d_in[2];
    const int*   se   = (const int*)d_in[3];
    const float* W0a  = (const float*)d_in[5];
    const float* b0a  = (const float*)d_in[6];
    const float* W0v  = (const float*)d_in[7];
    const float* b0v  = (const float*)d_in[8];
    const float* bn0g = (const float*)d_in[9];
    const float* bn0b = (const float*)d_in[10];
    const float* ec1g = (const float*)d_in[11];
    const float* ec1b = (const float*)d_in[12];
    const float* ecW1 = (const float*)d_in[13];
    const float* ec2g = (const float*)d_in[14];
    const float* ec2b = (const float*)d_in[15];
    const float* ecW2 = (const float*)d_in[16];
    const float* bng  = (const float*)d_in[17];
    const float* bnb  = (const float*)d_in[18];
    const float* fcaW = (const float*)d_in[19];
    const float* fcab = (const float*)d_in[20];
    const float* fcvW = (const float*)d_in[21];
    const float* fcvb = (const float*)d_in[22];
    const float* fcW  = (const float*)d_in[23];
    const float* fcb  = (const float*)d_in[24];
    float* out = (float*)d_out;

    const int GEMM_SMEM = (64 * APAD + 64 * WSTR) * 4;                 // 52224
    const int MSG_SMEM  = (MT_WORDS + 2 * 64 * WSTR + 128) * 4;        // 74240
    cudaFuncSetAttribute(msg_kernel,   cudaFuncAttributeMaxDynamicSharedMemorySize, MSG_SMEM);
    cudaFuncSetAttribute(lin0_kernel,  cudaFuncAttributeMaxDynamicSharedMemorySize, GEMM_SMEM);
    cudaFuncSetAttribute(fin_u_kernel, cudaFuncAttributeMaxDynamicSharedMemorySize, GEMM_SMEM);

    zero_kernel<<<(NN + 255) / 256, 256>>>();
    count_kernel<<<EE / 256, 256>>>(ei, dl, se);
    scan1_kernel<<<dim3(NBLK, 2), 1024>>>();
    scan2_kernel<<<1, 128>>>();
    scan3_kernel<<<dim3(NBLK, 2), 1024>>>();
    place_kernel<<<EE / 256, 256>>>(ei, dl, se);
    lin0_kernel<<<dim3((HALFN + 127) / 128, 2), 256, GEMM_SMEM>>>(x, W0a, b0a, W0v, b0v, bn0g, bn0b);

    int nuGrid  = (NN + 127) / 128;
    int finGrid = (NC + 255) / 256;

    // u for k=0 mask1 (features = gf)
    fin_u_kernel<<<nuGrid, 256, GEMM_SMEM>>>(-1, nullptr, nullptr, ec1g, ec1b, ecW1);

    for (int k = 0; k < 4; ++k) {
        const float* g1  = ec1g + k * 128;
        const float* b1  = ec1b + k * 128;
        const float* W1  = ecW1 + k * 8192;
        const float* g2  = ec2g + k * 64;
        const float* b2  = ec2b + k * 64;
        const float* W2  = ecW2 + k * 4096;
        int sel_cur = (k == 0) ? 0 : 2;

        msg_kernel<<<MSG_GRID, 256, MSG_SMEM>>>(sel_cur, 0, g1 + 64, b1 + 64, W1 + 4096, g2, b2, W2);
        fin_u_kernel<<<nuGrid, 256, GEMM_SMEM>>>(0, nullptr, nullptr, g1, b1, W1);
        msg_kernel<<<MSG_GRID, 256, MSG_SMEM>>>(1, 1, g1 + 64, b1 + 64, W1 + 4096, g2, b2, W2);
        if (k < 3) {
            int mode = (k == 0) ? 1 : 2;
            fin_u_kernel<<<nuGrid, 256, GEMM_SMEM>>>(mode, bng + k * 64, bnb + k * 64,
                ec1g + (k + 1) * 128, ec1b + (k + 1) * 128, ecW1 + (k + 1) * 8192);
        } else {
            finalize3_kernel<<<finGrid, 256>>>();
        }
    }
    heads_kernel<<<(NN + 255) / 256, 256>>>(fcW, fcb, fcaW, fcab, fcvW, fcvb, out);
}

// round 8
// speedup vs baseline: 1.5465x; 1.5292x over previous
#include <cuda_runtime.h>
#include <math.h>

#define NN 100000
#define EE 800000
#define HALFN 50000
#define NC (NN*64)
#define BNS 0.99999500003749969f  /* 1/sqrt(1+1e-5) */
#define APAD 132
#define WPAD 68
#define OPAD 72
#define MT_WORDS 9216   /* max(64*APAD=8448, 128*OPAD=9216) */
#define NBLK 98         /* ceil(NN/1024) */
#define MSG_GRID 444    /* 148 SMs x 3 resident blocks */

// ---------------- scratch (device globals) ----------------
static __device__ float d_gf[NC];
static __device__ float d_cur[NC];
static __device__ float d_h[NC];
static __device__ float d_acc[NC];
static __device__ float d_u[NC];
static __device__ int   d_ic1[NN], d_ic2[NN];       // per-dst counts
static __device__ int   d_off1[NN], d_off2[NN];     // start offsets (consumed as cursors)
static __device__ int   d_part[2 * 128];            // scan partials
static __device__ int   d_pofs[2 * 128];
static __device__ int   d_src1[EE], d_dst1[EE], d_src2[EE], d_dst2[EE];
static __device__ int   d_nact[2];

// ---------------- helpers ----------------
__device__ __forceinline__ unsigned f2tf(float x) {
    unsigned r;
    asm("cvt.rna.tf32.f32 %0, %1;" : "=r"(r) : "f"(x));
    return r;
}

__device__ __forceinline__ void mma_tf32(float c[4],
    unsigned a0, unsigned a1, unsigned a2, unsigned a3,
    unsigned b0, unsigned b1)
{
    asm volatile("mma.sync.aligned.m16n8k8.row.col.f32.tf32.tf32.f32 "
        "{%0,%1,%2,%3}, {%4,%5,%6,%7}, {%8,%9}, {%0,%1,%2,%3};\n"
        : "+f"(c[0]), "+f"(c[1]), "+f"(c[2]), "+f"(c[3])
        : "r"(a0), "r"(a1), "r"(a2), "r"(a3), "r"(b0), "r"(b1));
}

__device__ __forceinline__ void red4(float* p, float4 v) {
    asm volatile("red.global.add.v4.f32 [%0], {%1,%2,%3,%4};"
        :: "l"(p), "f"(v.x), "f"(v.y), "f"(v.z), "f"(v.w) : "memory");
}

// Warp computes rows [e0, e0+16) x all 64 cols, K = 64.
// At: k-major [64][APAD] (tf32 bits). Wt: n-major [64][WPAD] (Wt[n][k]=W[k][n]).
__device__ __forceinline__ void mma_chunk(const unsigned* At, const unsigned* Wt,
                                          int e0, int lane, float acc[8][4])
{
    int g = lane >> 2, la3 = lane & 3;
    const unsigned* Arow0 = At + la3 * APAD + e0 + g;
    const unsigned* Brow  = Wt + g * WPAD + la3;
#pragma unroll
    for (int ks = 0; ks < 64; ks += 8) {
        unsigned a0 = Arow0[ks * APAD];
        unsigned a1 = Arow0[ks * APAD + 8];
        unsigned a2 = Arow0[(ks + 4) * APAD];
        unsigned a3 = Arow0[(ks + 4) * APAD + 8];
#pragma unroll
        for (int nt = 0; nt < 8; nt++) {
            unsigned b0 = Brow[nt * 8 * WPAD + ks];
            unsigned b1 = Brow[nt * 8 * WPAD + ks + 4];
            mma_tf32(acc[nt], a0, a1, a2, a3, b0, b1);
        }
    }
}

// ---------------- zero ----------------
__global__ void zero_kernel() {
    int stride = gridDim.x * blockDim.x;
    for (int i = blockIdx.x * blockDim.x + threadIdx.x; i < NC; i += stride) {
        d_acc[i] = 0.f;
        if (i < NN) { d_ic1[i] = 0; d_ic2[i] = 0; }
        if (i < 2)  d_nact[i] = 0;
    }
}

// ---------------- counting sort by dst ----------------
__global__ void count_kernel(const int* __restrict__ ei,
                             const int* __restrict__ delta,
                             const int* __restrict__ selfE) {
    int e = blockIdx.x * blockDim.x + threadIdx.x;
    if (e >= EE) return;
    int d  = ei[EE + e];
    int dl = delta[e];
    int sf = selfE[e];
    if (dl < 1) atomicAdd(&d_ic1[d], 1);
    if ((dl >= 1 && dl < 4) || sf == 1) atomicAdd(&d_ic2[d], 1);
}

__global__ void scan1_kernel() {
    __shared__ int s[1024];
    int m = blockIdx.y;
    const int* ic = m ? d_ic2 : d_ic1;
    int* off = m ? d_off2 : d_off1;
    int tid = threadIdx.x;
    int i = blockIdx.x * 1024 + tid;
    int v = (i < NN) ? ic[i] : 0;
    s[tid] = v; __syncthreads();
#pragma unroll
    for (int o = 1; o < 1024; o <<= 1) {
        int t2 = (tid >= o) ? s[tid - o] : 0;
        __syncthreads();
        s[tid] += t2;
        __syncthreads();
    }
    if (i < NN) off[i] = s[tid] - v;
    if (tid == 1023) d_part[m * 128 + blockIdx.x] = s[1023];
}

__global__ void scan2_kernel() {
    __shared__ int s[128];
    int tid = threadIdx.x;
    for (int m = 0; m < 2; m++) {
        int v = (tid < NBLK) ? d_part[m * 128 + tid] : 0;
        s[tid] = v; __syncthreads();
#pragma unroll
        for (int o = 1; o < 128; o <<= 1) {
            int t2 = (tid >= o) ? s[tid - o] : 0;
            __syncthreads();
            s[tid] += t2;
            __syncthreads();
        }
        d_pofs[m * 128 + tid] = s[tid] - v;
        if (tid == NBLK - 1) d_nact[m] = s[NBLK - 1];
        __syncthreads();
    }
}

__global__ void scan3_kernel() {
    int m = blockIdx.y;
    int* off = m ? d_off2 : d_off1;
    int i = blockIdx.x * 1024 + threadIdx.x;
    if (i < NN) off[i] += d_pofs[m * 128 + blockIdx.x];
}

__global__ void place_kernel(const int* __restrict__ ei,
                             const int* __restrict__ delta,
                             const int* __restrict__ selfE) {
    int e = blockIdx.x * blockDim.x + threadIdx.x;
    if (e >= EE) return;
    int s  = ei[e];
    int d  = ei[EE + e];
    int dl = delta[e];
    int sf = selfE[e];
    if (dl < 1) {
        int pos = atomicAdd(&d_off1[d], 1);
        d_src1[pos] = s; d_dst1[pos] = d;
    }
    if ((dl >= 1 && dl < 4) || sf == 1) {
        int pos = atomicAdd(&d_off2[d], 1);
        d_src2[pos] = s; d_dst2[pos] = d;
    }
}

// ---------------- lin0: gf = relu(bn0(x[:,p,:] @ W + b)) via tf32 mma ----------------
__global__ __launch_bounds__(256) void lin0_kernel(
    const float* __restrict__ x,
    const float* __restrict__ W0a, const float* __restrict__ b0a,
    const float* __restrict__ W0v, const float* __restrict__ b0v,
    const float* __restrict__ bn0g, const float* __restrict__ bn0b)
{
    extern __shared__ unsigned smu[];
    unsigned* At = smu;            // 64*APAD
    unsigned* Wt = smu + 64 * APAD;
    int p = blockIdx.y;
    const float* W    = p ? W0v : W0a;
    const float* bias = p ? b0v : b0a;
    int t = threadIdx.x;
    int hbase = blockIdx.x * 128;
    int warp = t >> 5, lane = t & 31, e0 = warp * 16, g = lane >> 2, la3 = lane & 3;

    float acc[8][4];
#pragma unroll
    for (int i = 0; i < 8; i++)
#pragma unroll
        for (int j = 0; j < 4; j++) acc[i][j] = 0.f;

    for (int kc = 0; kc < 512; kc += 64) {
#pragma unroll
        for (int s = 0; s < 8; s++) {
            int idx = t + s * 256;
            int row = idx & 127, q = idx >> 7;
            int half = hbase + row;
            float4 v = make_float4(0.f, 0.f, 0.f, 0.f);
            if (half < HALFN) {
                int node = half * 2 + p;
                v = __ldg((const float4*)(x + (size_t)node * 1024 + (size_t)p * 512 + kc) + q);
            }
            unsigned* Ap = At + q * 4 * APAD + row;
            Ap[0]        = f2tf(v.x);
            Ap[APAD]     = f2tf(v.y);
            Ap[2 * APAD] = f2tf(v.z);
            Ap[3 * APAD] = f2tf(v.w);
        }
#pragma unroll
        for (int s = 0; s < 16; s++) {
            int idx = t + s * 256;
            int kk = idx >> 6, n = idx & 63;
            Wt[n * WPAD + kk] = f2tf(__ldg(W + (size_t)(kc + kk) * 64 + n));
        }
        __syncthreads();
        mma_chunk(At, Wt, e0, lane, acc);
        __syncthreads();
    }
    int half1 = hbase + e0 + g, half2 = half1 + 8;
#pragma unroll
    for (int nt = 0; nt < 8; nt++) {
        int c = nt * 8 + 2 * la3;
        float2 bs = __ldg((const float2*)(bias + c));
        float2 gg = __ldg((const float2*)(bn0g + c));
        float2 bb = __ldg((const float2*)(bn0b + c));
        if (half1 < HALFN) {
            int node = half1 * 2 + p;
            float v0 = fmaxf((acc[nt][0] + bs.x) * (BNS * gg.x) + bb.x, 0.f);
            float v1 = fmaxf((acc[nt][1] + bs.y) * (BNS * gg.y) + bb.y, 0.f);
            *(float2*)(d_gf + (size_t)node * 64 + c) = make_float2(v0, v1);
        }
        if (half2 < HALFN) {
            int node = half2 * 2 + p;
            float v2 = fmaxf((acc[nt][2] + bs.x) * (BNS * gg.x) + bb.x, 0.f);
            float v3 = fmaxf((acc[nt][3] + bs.y) * (BNS * gg.y) + bb.y, 0.f);
            *(float2*)(d_gf + (size_t)node * 64 + c) = make_float2(v2, v3);
        }
    }
}

// ---------------- node_u: u = relu(bn1a(xf)) @ W1a (per node) ----------------
__global__ __launch_bounds__(256) void node_u_kernel(
    int sel, const float* __restrict__ g1, const float* __restrict__ b1,
    const float* __restrict__ W1a)
{
    extern __shared__ unsigned smu[];
    unsigned* At = smu;
    unsigned* Wt = smu + 64 * APAD;
    const float* xf = (sel == 0) ? d_gf : (sel == 1 ? d_h : d_cur);
    int t = threadIdx.x;
    int rbase = blockIdx.x * 128;

#pragma unroll
    for (int s = 0; s < 16; s++) {
        int idx = t + s * 256;
        int kk = idx >> 6, n = idx & 63;
        Wt[n * WPAD + kk] = f2tf(__ldg(W1a + (size_t)kk * 64 + n));
    }
#pragma unroll
    for (int s = 0; s < 8; s++) {
        int idx = t + s * 256;
        int row = idx & 127, q = idx >> 7;
        int node = rbase + row;
        unsigned* Ap = At + q * 4 * APAD + row;
        if (node < NN) {
            float4 v  = __ldg((const float4*)(xf + (size_t)node * 64) + q);
            float4 sg = __ldg((const float4*)g1 + q);
            float4 sb = __ldg((const float4*)b1 + q);
            Ap[0]        = f2tf(fmaxf(v.x * (BNS * sg.x) + sb.x, 0.f));
            Ap[APAD]     = f2tf(fmaxf(v.y * (BNS * sg.y) + sb.y, 0.f));
            Ap[2 * APAD] = f2tf(fmaxf(v.z * (BNS * sg.z) + sb.z, 0.f));
            Ap[3 * APAD] = f2tf(fmaxf(v.w * (BNS * sg.w) + sb.w, 0.f));
        } else {
            Ap[0] = Ap[APAD] = Ap[2 * APAD] = Ap[3 * APAD] = 0u;
        }
    }
    __syncthreads();

    int warp = t >> 5, lane = t & 31, e0 = warp * 16, g = lane >> 2, la3 = lane & 3;
    float acc[8][4];
#pragma unroll
    for (int i = 0; i < 8; i++)
#pragma unroll
        for (int j = 0; j < 4; j++) acc[i][j] = 0.f;
    mma_chunk(At, Wt, e0, lane, acc);

    int n1 = rbase + e0 + g, n2 = n1 + 8;
#pragma unroll
    for (int nt = 0; nt < 8; nt++) {
        int c = nt * 8 + 2 * la3;
        if (n1 < NN) *(float2*)(d_u + (size_t)n1 * 64 + c) = make_float2(acc[nt][0], acc[nt][1]);
        if (n2 < NN) *(float2*)(d_u + (size_t)n2 * 64 + c) = make_float2(acc[nt][2], acc[nt][3]);
    }
}

// ---------------- EdgeConv message kernel (persistent blocks, R4 inner body) ----------------
__global__ __launch_bounds__(256, 3) void msg_kernel(
    int sel, int maskid,
    const float* __restrict__ g1b, const float* __restrict__ b1b, const float* __restrict__ W1b,
    const float* __restrict__ g2,  const float* __restrict__ b2,  const float* __restrict__ W2)
{
    extern __shared__ unsigned smu[];
    unsigned* Mt  = smu;                    // MT_WORDS region (GEMM A / H1, then output tile)
    float*    Ot  = (float*)smu;            // 128 x OPAD fp32 output tile (aliases Mt)
    unsigned* Wt1 = smu + MT_WORDS;
    unsigned* Wt2 = Wt1 + 64 * WPAD;
    int* dsts = (int*)(Wt2 + 64 * WPAD);    // 128 ints

    int count = d_nact[maskid];
    if (blockIdx.x * 128 >= count) return;  // uniform per block
    const float* xf = (sel == 0) ? d_gf : (sel == 1 ? d_h : d_cur);
    const int* srcL = maskid ? d_src2 : d_src1;
    const int* dstL = maskid ? d_dst2 : d_dst1;
    int t = threadIdx.x;
    int warp = t >> 5, lane = t & 31, e0 = warp * 16, g = lane >> 2, la3 = lane & 3;
    int e_loc = t & 127, h = t >> 7;

    // weights staged ONCE per persistent block
#pragma unroll
    for (int s = 0; s < 16; s++) {
        int idx = t + s * 256;
        int kk = idx >> 6, n = idx & 63;
        Wt1[n * WPAD + kk] = f2tf(__ldg(W1b + (size_t)kk * 64 + n));
        Wt2[n * WPAD + kk] = f2tf(__ldg(W2  + (size_t)kk * 64 + n));
    }

    for (int tile = blockIdx.x; tile * 128 < count; tile += gridDim.x) {
        int base = tile * 128;
        // gather diff -> bn1b -> relu -> tf32 -> Mt (k-major)
        {
            int e = base + e_loc;
            int act = (e < count);
            int sN = 0, dN = 0;
            if (act) { sN = srcL[e]; dN = dstL[e]; }
            if (h == 0) dsts[e_loc] = act ? dN : -1;
            const float4* xi4 = (const float4*)(xf + (size_t)dN * 64) + h * 8;
            const float4* xj4 = (const float4*)(xf + (size_t)sN * 64) + h * 8;
#pragma unroll
            for (int q = 0; q < 8; q++) {
                float4 a  = __ldg(xi4 + q);
                float4 bv = __ldg(xj4 + q);
                int k = h * 32 + q * 4;
                float4 sg = __ldg((const float4*)g1b + (k >> 2));
                float4 sb = __ldg((const float4*)b1b + (k >> 2));
                unsigned* Mp = Mt + k * APAD + e_loc;
                Mp[0]        = f2tf(fmaxf((bv.x - a.x) * (BNS * sg.x) + sb.x, 0.f));
                Mp[APAD]     = f2tf(fmaxf((bv.y - a.y) * (BNS * sg.y) + sb.y, 0.f));
                Mp[2 * APAD] = f2tf(fmaxf((bv.z - a.z) * (BNS * sg.z) + sb.z, 0.f));
                Mp[3 * APAD] = f2tf(fmaxf((bv.w - a.w) * (BNS * sg.w) + sb.w, 0.f));
            }
        }
        __syncthreads();

        float acc[8][4];
#pragma unroll
        for (int i = 0; i < 8; i++)
#pragma unroll
            for (int j = 0; j < 4; j++) acc[i][j] = 0.f;
        mma_chunk(Mt, Wt1, e0, lane, acc);

        // epilogue1: H1 = relu(bn2(acc + u[dst])) -> back into Mt (own e-columns only)
        int d1 = dsts[e0 + g], d2 = dsts[e0 + g + 8];
#pragma unroll
        for (int nt = 0; nt < 8; nt++) {
            int c = nt * 8 + 2 * la3;
            float2 gg = __ldg((const float2*)(g2 + c));
            float2 bb = __ldg((const float2*)(b2 + c));
            float u0 = 0.f, u1 = 0.f, u2 = 0.f, u3 = 0.f;
            if (d1 >= 0) { float2 u = __ldg((const float2*)(d_u + (size_t)d1 * 64 + c)); u0 = u.x; u1 = u.y; }
            if (d2 >= 0) { float2 u = __ldg((const float2*)(d_u + (size_t)d2 * 64 + c)); u2 = u.x; u3 = u.y; }
            float h00 = fmaxf((acc[nt][0] + u0) * (BNS * gg.x) + bb.x, 0.f);
            float h01 = fmaxf((acc[nt][1] + u1) * (BNS * gg.y) + bb.y, 0.f);
            float h10 = fmaxf((acc[nt][2] + u2) * (BNS * gg.x) + bb.x, 0.f);
            float h11 = fmaxf((acc[nt][3] + u3) * (BNS * gg.y) + bb.y, 0.f);
            Mt[c * APAD + e0 + g]           = f2tf(h00);
            Mt[(c + 1) * APAD + e0 + g]     = f2tf(h01);
            Mt[c * APAD + e0 + g + 8]       = f2tf(h10);
            Mt[(c + 1) * APAD + e0 + g + 8] = f2tf(h11);
        }
        __syncwarp();

        float acc2[8][4];
#pragma unroll
        for (int i = 0; i < 8; i++)
#pragma unroll
            for (int j = 0; j < 4; j++) acc2[i][j] = 0.f;
        mma_chunk(Mt, Wt2, e0, lane, acc2);

        __syncthreads();
#pragma unroll
        for (int nt = 0; nt < 8; nt++) {
            int c = nt * 8 + 2 * la3;
            *(float2*)(Ot + (e0 + g) * OPAD + c)     = make_float2(acc2[nt][0], acc2[nt][1]);
            *(float2*)(Ot + (e0 + g + 8) * OPAD + c) = make_float2(acc2[nt][2], acc2[nt][3]);
        }
        __syncthreads();

        // segmented reduction over sorted dsts: one red.v4 per (segment, 4-col chunk)
        {
            int cc = t & 15;
            int rg = t >> 4;
            float4 sum = make_float4(0.f, 0.f, 0.f, 0.f);
            int cur = -1;
#pragma unroll
            for (int i = 0; i < 8; i++) {
                int r = rg * 8 + i;
                int dd = dsts[r];
                float4 v = *(const float4*)(Ot + r * OPAD + cc * 4);
                if (dd != cur) {
                    if (cur >= 0) red4(d_acc + (size_t)cur * 64 + cc * 4, sum);
                    cur = dd;
                    sum = v;
                } else {
                    sum.x += v.x; sum.y += v.y; sum.z += v.z; sum.w += v.w;
                }
            }
            if (cur >= 0) red4(d_acc + (size_t)cur * 64 + cc * 4, sum);
        }
        __syncthreads();   // protect Mt/Ot/dsts reuse by next tile
    }
}

// ---------------- finalize: mean (+residual) (+bn+relu), re-zero acc ----------------
__global__ void finalize_kernel(int mode, const float* __restrict__ bng, const float* __restrict__ bnb) {
    int i = blockIdx.x * blockDim.x + threadIdx.x;
    if (i >= NC) return;
    int n = i >> 6, c = i & 63;
    const int* cnt = (mode == 0) ? d_ic1 : d_ic2;
    float v = d_acc[i] / fmaxf((float)cnt[n], 1.f);
    d_acc[i] = 0.f;
    if (mode >= 2) v += d_cur[i];
    if (mode == 1 || mode == 2) v = fmaxf(v * (BNS * bng[c]) + bnb[c], 0.f);
    if (mode == 0) d_h[i] = v; else d_cur[i] = v;
}

// ---------------- heads ----------------
__global__ void heads_kernel(const float* __restrict__ fcW, const float* __restrict__ fcb,
                             const float* __restrict__ fcaW, const float* __restrict__ fcab,
                             const float* __restrict__ fcvW, const float* __restrict__ fcvb,
                             float* __restrict__ out)
{
    int n = blockIdx.x * blockDim.x + threadIdx.x;
    if (n >= NN) return;
    const float* f = d_cur + (size_t)n * 64;
    const float* g = d_gf  + (size_t)n * 64;
    bool even = (n & 1) == 0;
    const float* hw = even ? fcaW : fcvW;
    const float* hb = even ? fcab : fcvb;
    float o0 = fcb[0], o1 = fcb[1], h0 = hb[0], h1 = hb[1];
#pragma unroll 8
    for (int c = 0; c < 64; ++c) {
        float fv = f[c], gv = g[c];
        o0 += fv * fcW[2 * c];  o1 += fv * fcW[2 * c + 1];
        h0 += gv * hw[2 * c];   h1 += gv * hw[2 * c + 1];
    }
    out[2 * n] = o0; out[2 * n + 1] = o1;
    size_t off = even ? (size_t)2 * NN + (size_t)(n >> 1) * 2
                      : (size_t)2 * NN + (size_t)2 * HALFN + (size_t)(n >> 1) * 2;
    out[off] = h0; out[off + 1] = h1;
}

// ---------------- launch ----------------
extern "C" void kernel_launch(void* const* d_in, const int* in_sizes, int n_in,
                              void* d_out, int out_size) {
    const float* x    = (const float*)d_in[0];
    const int*   ei   = (const int*)d_in[1];
    const int*   dl   = (const int*)d_in[2];
    const int*   se   = (const int*)d_in[3];
    const float* W0a  = (const float*)d_in[5];
    const float* b0a  = (const float*)d_in[6];
    const float* W0v  = (const float*)d_in[7];
    const float* b0v  = (const float*)d_in[8];
    const float* bn0g = (const float*)d_in[9];
    const float* bn0b = (const float*)d_in[10];
    const float* ec1g = (const float*)d_in[11];
    const float* ec1b = (const float*)d_in[12];
    const float* ecW1 = (const float*)d_in[13];
    const float* ec2g = (const float*)d_in[14];
    const float* ec2b = (const float*)d_in[15];
    const float* ecW2 = (const float*)d_in[16];
    const float* bng  = (const float*)d_in[17];
    const float* bnb  = (const float*)d_in[18];
    const float* fcaW = (const float*)d_in[19];
    const float* fcab = (const float*)d_in[20];
    const float* fcvW = (const float*)d_in[21];
    const float* fcvb = (const float*)d_in[22];
    const float* fcW  = (const float*)d_in[23];
    const float* fcb  = (const float*)d_in[24];
    float* out = (float*)d_out;

    const int GEMM_SMEM = (64 * APAD + 64 * WPAD) * 4;                 // 51200
    const int MSG_SMEM  = (MT_WORDS + 2 * 64 * WPAD + 128) * 4;        // 72192
    cudaFuncSetAttribute(msg_kernel,    cudaFuncAttributeMaxDynamicSharedMemorySize, MSG_SMEM);
    cudaFuncSetAttribute(lin0_kernel,   cudaFuncAttributeMaxDynamicSharedMemorySize, GEMM_SMEM);
    cudaFuncSetAttribute(node_u_kernel, cudaFuncAttributeMaxDynamicSharedMemorySize, GEMM_SMEM);

    zero_kernel<<<1024, 256>>>();
    count_kernel<<<EE / 256, 256>>>(ei, dl, se);
    scan1_kernel<<<dim3(NBLK, 2), 1024>>>();
    scan2_kernel<<<1, 128>>>();
    scan3_kernel<<<dim3(NBLK, 2), 1024>>>();
    place_kernel<<<EE / 256, 256>>>(ei, dl, se);
    lin0_kernel<<<dim3((HALFN + 127) / 128, 2), 256, GEMM_SMEM>>>(x, W0a, b0a, W0v, b0v, bn0g, bn0b);

    int nuGrid  = (NN + 127) / 128;
    int finGrid = (NC + 255) / 256;
    for (int k = 0; k < 4; ++k) {
        const float* g1  = ec1g + k * 128;
        const float* b1  = ec1b + k * 128;
        const float* W1  = ecW1 + k * 8192;
        const float* g2  = ec2g + k * 64;
        const float* b2  = ec2b + k * 64;
        const float* W2  = ecW2 + k * 4096;
        int sel_cur = (k == 0) ? 0 : 2;

        node_u_kernel<<<nuGrid, 256, GEMM_SMEM>>>(sel_cur, g1, b1, W1);
        msg_kernel<<<MSG_GRID, 256, MSG_SMEM>>>(sel_cur, 0, g1 + 64, b1 + 64, W1 + 4096, g2, b2, W2);
        finalize_kernel<<<finGrid, 256>>>(0, nullptr, nullptr);

        node_u_kernel<<<nuGrid, 256, GEMM_SMEM>>>(1, g1, b1, W1);
        msg_kernel<<<MSG_GRID, 256, MSG_SMEM>>>(1, 1, g1 + 64, b1 + 64, W1 + 4096, g2, b2, W2);
        int mode = (k == 0) ? 1 : (k == 3 ? 3 : 2);
        const float* gB = (k < 3) ? bng + k * 64 : nullptr;
        const float* bB = (k < 3) ? bnb + k * 64 : nullptr;
        finalize_kernel<<<finGrid, 256>>>(mode, gB, bB);
    }
    heads_kernel<<<(NN + 255) / 256, 256>>>(fcW, fcb, fcaW, fcab, fcvW, fcvb, out);
}

// round 9
// speedup vs baseline: 2.3475x; 1.5179x over previous
#include <cuda_runtime.h>
#include <math.h>

#define NN 100000
#define EE 800000
#define HALFN 50000
#define NC (NN*64)
#define BNS 0.99999500003749969f  /* 1/sqrt(1+1e-5) */
#define APAD 132
#define WPAD 68
#define OPAD 72
#define MT_WORDS 9216   /* max(64*APAD=8448, 128*OPAD=9216) */
#define NBLK 98         /* ceil(NN/1024) */

// ---------------- scratch (device globals) ----------------
static __device__ float d_gf[NC];
static __device__ float d_cur[NC];
static __device__ float d_h[NC];
static __device__ float d_acc[NC];
static __device__ float d_u[NC];
static __device__ int   d_ic1[NN], d_ic2[NN];       // per-dst counts
static __device__ int   d_off1[NN], d_off2[NN];     // start offsets (consumed as cursors)
static __device__ int   d_part[2 * 128];            // scan partials
static __device__ int   d_pofs[2 * 128];
static __device__ int   d_src1[EE], d_dst1[EE], d_src2[EE], d_dst2[EE];
static __device__ int   d_nact[2];

// ---------------- helpers ----------------
__device__ __forceinline__ unsigned f2tf(float x) {
    unsigned r;
    asm("cvt.rna.tf32.f32 %0, %1;" : "=r"(r) : "f"(x));
    return r;
}

__device__ __forceinline__ void mma_tf32(float c[4],
    unsigned a0, unsigned a1, unsigned a2, unsigned a3,
    unsigned b0, unsigned b1)
{
    asm volatile("mma.sync.aligned.m16n8k8.row.col.f32.tf32.tf32.f32 "
        "{%0,%1,%2,%3}, {%4,%5,%6,%7}, {%8,%9}, {%0,%1,%2,%3};\n"
        : "+f"(c[0]), "+f"(c[1]), "+f"(c[2]), "+f"(c[3])
        : "r"(a0), "r"(a1), "r"(a2), "r"(a3), "r"(b0), "r"(b1));
}

__device__ __forceinline__ void red4(float* p, float4 v) {
    asm volatile("red.global.add.v4.f32 [%0], {%1,%2,%3,%4};"
        :: "l"(p), "f"(v.x), "f"(v.y), "f"(v.z), "f"(v.w) : "memory");
}

// Warp computes rows [e0, e0+16) x all 64 cols, K = 64.
// At: k-major [64][APAD] (tf32 bits). Wt: n-major [64][WPAD] (Wt[n][k]=W[k][n]).
__device__ __forceinline__ void mma_chunk(const unsigned* At, const unsigned* Wt,
                                          int e0, int lane, float acc[8][4])
{
    int g = lane >> 2, la3 = lane & 3;
    const unsigned* Arow0 = At + la3 * APAD + e0 + g;
    const unsigned* Brow  = Wt + g * WPAD + la3;
#pragma unroll
    for (int ks = 0; ks < 64; ks += 8) {
        unsigned a0 = Arow0[ks * APAD];
        unsigned a1 = Arow0[ks * APAD + 8];
        unsigned a2 = Arow0[(ks + 4) * APAD];
        unsigned a3 = Arow0[(ks + 4) * APAD + 8];
#pragma unroll
        for (int nt = 0; nt < 8; nt++) {
            unsigned b0 = Brow[nt * 8 * WPAD + ks];
            unsigned b1 = Brow[nt * 8 * WPAD + ks + 4];
            mma_tf32(acc[nt], a0, a1, a2, a3, b0, b1);
        }
    }
}

// ---------------- zero ----------------
__global__ void zero_kernel() {
    int stride = gridDim.x * blockDim.x;
    for (int i = blockIdx.x * blockDim.x + threadIdx.x; i < NC; i += stride) {
        d_acc[i] = 0.f;
        if (i < NN) { d_ic1[i] = 0; d_ic2[i] = 0; }
        if (i < 2)  d_nact[i] = 0;
    }
}

// ---------------- counting sort by dst ----------------
__global__ void count_kernel(const int* __restrict__ ei,
                             const int* __restrict__ delta,
                             const int* __restrict__ selfE) {
    int e = blockIdx.x * blockDim.x + threadIdx.x;
    if (e >= EE) return;
    int d  = ei[EE + e];
    int dl = delta[e];
    int sf = selfE[e];
    if (dl < 1) atomicAdd(&d_ic1[d], 1);
    if ((dl >= 1 && dl < 4) || sf == 1) atomicAdd(&d_ic2[d], 1);
}

__global__ void scan1_kernel() {
    __shared__ int s[1024];
    int m = blockIdx.y;
    const int* ic = m ? d_ic2 : d_ic1;
    int* off = m ? d_off2 : d_off1;
    int tid = threadIdx.x;
    int i = blockIdx.x * 1024 + tid;
    int v = (i < NN) ? ic[i] : 0;
    s[tid] = v; __syncthreads();
#pragma unroll
    for (int o = 1; o < 1024; o <<= 1) {
        int t2 = (tid >= o) ? s[tid - o] : 0;
        __syncthreads();
        s[tid] += t2;
        __syncthreads();
    }
    if (i < NN) off[i] = s[tid] - v;
    if (tid == 1023) d_part[m * 128 + blockIdx.x] = s[1023];
}

__global__ void scan2_kernel() {
    __shared__ int s[128];
    int tid = threadIdx.x;
    for (int m = 0; m < 2; m++) {
        int v = (tid < NBLK) ? d_part[m * 128 + tid] : 0;
        s[tid] = v; __syncthreads();
#pragma unroll
        for (int o = 1; o < 128; o <<= 1) {
            int t2 = (tid >= o) ? s[tid - o] : 0;
            __syncthreads();
            s[tid] += t2;
            __syncthreads();
        }
        d_pofs[m * 128 + tid] = s[tid] - v;
        if (tid == NBLK - 1) d_nact[m] = s[NBLK - 1];
        __syncthreads();
    }
}

__global__ void scan3_kernel() {
    int m = blockIdx.y;
    int* off = m ? d_off2 : d_off1;
    int i = blockIdx.x * 1024 + threadIdx.x;
    if (i < NN) off[i] += d_pofs[m * 128 + blockIdx.x];
}

__global__ void place_kernel(const int* __restrict__ ei,
                             const int* __restrict__ delta,
                             const int* __restrict__ selfE) {
    int e = blockIdx.x * blockDim.x + threadIdx.x;
    if (e >= EE) return;
    int s  = ei[e];
    int d  = ei[EE + e];
    int dl = delta[e];
    int sf = selfE[e];
    if (dl < 1) {
        int pos = atomicAdd(&d_off1[d], 1);
        d_src1[pos] = s; d_dst1[pos] = d;
    }
    if ((dl >= 1 && dl < 4) || sf == 1) {
        int pos = atomicAdd(&d_off2[d], 1);
        d_src2[pos] = s; d_dst2[pos] = d;
    }
}

// ---------------- lin0: gf = relu(bn0(x[:,p,:] @ W + b)) via tf32 mma ----------------
__global__ __launch_bounds__(256) void lin0_kernel(
    const float* __restrict__ x,
    const float* __restrict__ W0a, const float* __restrict__ b0a,
    const float* __restrict__ W0v, const float* __restrict__ b0v,
    const float* __restrict__ bn0g, const float* __restrict__ bn0b)
{
    extern __shared__ unsigned smu[];
    unsigned* At = smu;            // 64*APAD
    unsigned* Wt = smu + 64 * APAD;
    int p = blockIdx.y;
    const float* W    = p ? W0v : W0a;
    const float* bias = p ? b0v : b0a;
    int t = threadIdx.x;
    int hbase = blockIdx.x * 128;
    int warp = t >> 5, lane = t & 31, e0 = warp * 16, g = lane >> 2, la3 = lane & 3;

    float acc[8][4];
#pragma unroll
    for (int i = 0; i < 8; i++)
#pragma unroll
        for (int j = 0; j < 4; j++) acc[i][j] = 0.f;

    for (int kc = 0; kc < 512; kc += 64) {
#pragma unroll
        for (int s = 0; s < 8; s++) {
            int idx = t + s * 256;
            int row = idx & 127, q = idx >> 7;
            int half = hbase + row;
            float4 v = make_float4(0.f, 0.f, 0.f, 0.f);
            if (half < HALFN) {
                int node = half * 2 + p;
                v = __ldg((const float4*)(x + (size_t)node * 1024 + (size_t)p * 512 + kc) + q);
            }
            unsigned* Ap = At + q * 4 * APAD + row;
            Ap[0]        = f2tf(v.x);
            Ap[APAD]     = f2tf(v.y);
            Ap[2 * APAD] = f2tf(v.z);
            Ap[3 * APAD] = f2tf(v.w);
        }
#pragma unroll
        for (int s = 0; s < 16; s++) {
            int idx = t + s * 256;
            int kk = idx >> 6, n = idx & 63;
            Wt[n * WPAD + kk] = f2tf(__ldg(W + (size_t)(kc + kk) * 64 + n));
        }
        __syncthreads();
        mma_chunk(At, Wt, e0, lane, acc);
        __syncthreads();
    }
    int half1 = hbase + e0 + g, half2 = half1 + 8;
#pragma unroll
    for (int nt = 0; nt < 8; nt++) {
        int c = nt * 8 + 2 * la3;
        float2 bs = __ldg((const float2*)(bias + c));
        float2 gg = __ldg((const float2*)(bn0g + c));
        float2 bb = __ldg((const float2*)(bn0b + c));
        if (half1 < HALFN) {
            int node = half1 * 2 + p;
            float v0 = fmaxf((acc[nt][0] + bs.x) * (BNS * gg.x) + bb.x, 0.f);
            float v1 = fmaxf((acc[nt][1] + bs.y) * (BNS * gg.y) + bb.y, 0.f);
            *(float2*)(d_gf + (size_t)node * 64 + c) = make_float2(v0, v1);
        }
        if (half2 < HALFN) {
            int node = half2 * 2 + p;
            float v2 = fmaxf((acc[nt][2] + bs.x) * (BNS * gg.x) + bb.x, 0.f);
            float v3 = fmaxf((acc[nt][3] + bs.y) * (BNS * gg.y) + bb.y, 0.f);
            *(float2*)(d_gf + (size_t)node * 64 + c) = make_float2(v2, v3);
        }
    }
}

// ---------------- node_u: u = relu(bn1a(xf)) @ W1a (per node) ----------------
__global__ __launch_bounds__(256) void node_u_kernel(
    int sel, const float* __restrict__ g1, const float* __restrict__ b1,
    const float* __restrict__ W1a)
{
    extern __shared__ unsigned smu[];
    unsigned* At = smu;
    unsigned* Wt = smu + 64 * APAD;
    const float* xf = (sel == 0) ? d_gf : (sel == 1 ? d_h : d_cur);
    int t = threadIdx.x;
    int rbase = blockIdx.x * 128;

#pragma unroll
    for (int s = 0; s < 16; s++) {
        int idx = t + s * 256;
        int kk = idx >> 6, n = idx & 63;
        Wt[n * WPAD + kk] = f2tf(__ldg(W1a + (size_t)kk * 64 + n));
    }
#pragma unroll
    for (int s = 0; s < 8; s++) {
        int idx = t + s * 256;
        int row = idx & 127, q = idx >> 7;
        int node = rbase + row;
        unsigned* Ap = At + q * 4 * APAD + row;
        if (node < NN) {
            float4 v  = __ldg((const float4*)(xf + (size_t)node * 64) + q);
            float4 sg = __ldg((const float4*)g1 + q);
            float4 sb = __ldg((const float4*)b1 + q);
            Ap[0]        = f2tf(fmaxf(v.x * (BNS * sg.x) + sb.x, 0.f));
            Ap[APAD]     = f2tf(fmaxf(v.y * (BNS * sg.y) + sb.y, 0.f));
            Ap[2 * APAD] = f2tf(fmaxf(v.z * (BNS * sg.z) + sb.z, 0.f));
            Ap[3 * APAD] = f2tf(fmaxf(v.w * (BNS * sg.w) + sb.w, 0.f));
        } else {
            Ap[0] = Ap[APAD] = Ap[2 * APAD] = Ap[3 * APAD] = 0u;
        }
    }
    __syncthreads();

    int warp = t >> 5, lane = t & 31, e0 = warp * 16, g = lane >> 2, la3 = lane & 3;
    float acc[8][4];
#pragma unroll
    for (int i = 0; i < 8; i++)
#pragma unroll
        for (int j = 0; j < 4; j++) acc[i][j] = 0.f;
    mma_chunk(At, Wt, e0, lane, acc);

    int n1 = rbase + e0 + g, n2 = n1 + 8;
#pragma unroll
    for (int nt = 0; nt < 8; nt++) {
        int c = nt * 8 + 2 * la3;
        if (n1 < NN) *(float2*)(d_u + (size_t)n1 * 64 + c) = make_float2(acc[nt][0], acc[nt][1]);
        if (n2 < NN) *(float2*)(d_u + (size_t)n2 * 64 + c) = make_float2(acc[nt][2], acc[nt][3]);
    }
}

// ---------------- EdgeConv message kernel (tf32 mma, sorted dsts, seg-reduced scatter) ----------------
__global__ __launch_bounds__(256, 3) void msg_kernel(
    int sel, int maskid,
    const float* __restrict__ g1b, const float* __restrict__ b1b, const float* __restrict__ W1b,
    const float* __restrict__ g2,  const float* __restrict__ b2,  const float* __restrict__ W2)
{
    extern __shared__ unsigned smu[];
    unsigned* Mt  = smu;                    // MT_WORDS region (GEMM A / H1, then output tile)
    float*    Ot  = (float*)smu;            // 128 x OPAD fp32 output tile (aliases Mt)
    unsigned* Wt1 = smu + MT_WORDS;
    unsigned* Wt2 = Wt1 + 64 * WPAD;
    int* dsts = (int*)(Wt2 + 64 * WPAD);    // 128 ints

    int count = d_nact[maskid];
    int base = blockIdx.x * 128;
    if (base >= count) return;
    const float* xf = (sel == 0) ? d_gf : (sel == 1 ? d_h : d_cur);
    const int* srcL = maskid ? d_src2 : d_src1;
    const int* dstL = maskid ? d_dst2 : d_dst1;
    int t = threadIdx.x;

#pragma unroll
    for (int s = 0; s < 16; s++) {
        int idx = t + s * 256;
        int kk = idx >> 6, n = idx & 63;
        Wt1[n * WPAD + kk] = f2tf(__ldg(W1b + (size_t)kk * 64 + n));
        Wt2[n * WPAD + kk] = f2tf(__ldg(W2  + (size_t)kk * 64 + n));
    }
    // gather diff -> bn1b -> relu -> tf32 -> Mt (k-major)
    {
        int e_loc = t & 127, h = t >> 7;
        int e = base + e_loc;
        int act = (e < count);
        int sN = 0, dN = 0;
        if (act) { sN = srcL[e]; dN = dstL[e]; }
        if (h == 0) dsts[e_loc] = act ? dN : -1;
        const float4* xi4 = (const float4*)(xf + (size_t)dN * 64) + h * 8;
        const float4* xj4 = (const float4*)(xf + (size_t)sN * 64) + h * 8;
#pragma unroll
        for (int q = 0; q < 8; q++) {
            float4 a  = __ldg(xi4 + q);
            float4 bv = __ldg(xj4 + q);
            int k = h * 32 + q * 4;
            float4 sg = __ldg((const float4*)g1b + (k >> 2));
            float4 sb = __ldg((const float4*)b1b + (k >> 2));
            unsigned* Mp = Mt + k * APAD + e_loc;
            Mp[0]        = f2tf(fmaxf((bv.x - a.x) * (BNS * sg.x) + sb.x, 0.f));
            Mp[APAD]     = f2tf(fmaxf((bv.y - a.y) * (BNS * sg.y) + sb.y, 0.f));
            Mp[2 * APAD] = f2tf(fmaxf((bv.z - a.z) * (BNS * sg.z) + sb.z, 0.f));
            Mp[3 * APAD] = f2tf(fmaxf((bv.w - a.w) * (BNS * sg.w) + sb.w, 0.f));
        }
    }
    __syncthreads();

    int warp = t >> 5, lane = t & 31, e0 = warp * 16, g = lane >> 2, la3 = lane & 3;
    float acc[8][4];
#pragma unroll
    for (int i = 0; i < 8; i++)
#pragma unroll
        for (int j = 0; j < 4; j++) acc[i][j] = 0.f;
    mma_chunk(Mt, Wt1, e0, lane, acc);

    // epilogue1: H1 = relu(bn2(acc + u[dst])) -> back into Mt (own e-columns only)
    int d1 = dsts[e0 + g], d2 = dsts[e0 + g + 8];
#pragma unroll
    for (int nt = 0; nt < 8; nt++) {
        int c = nt * 8 + 2 * la3;
        float2 gg = __ldg((const float2*)(g2 + c));
        float2 bb = __ldg((const float2*)(b2 + c));
        float u0 = 0.f, u1 = 0.f, u2 = 0.f, u3 = 0.f;
        if (d1 >= 0) { float2 u = __ldg((const float2*)(d_u + (size_t)d1 * 64 + c)); u0 = u.x; u1 = u.y; }
        if (d2 >= 0) { float2 u = __ldg((const float2*)(d_u + (size_t)d2 * 64 + c)); u2 = u.x; u3 = u.y; }
        float h00 = fmaxf((acc[nt][0] + u0) * (BNS * gg.x) + bb.x, 0.f);
        float h01 = fmaxf((acc[nt][1] + u1) * (BNS * gg.y) + bb.y, 0.f);
        float h10 = fmaxf((acc[nt][2] + u2) * (BNS * gg.x) + bb.x, 0.f);
        float h11 = fmaxf((acc[nt][3] + u3) * (BNS * gg.y) + bb.y, 0.f);
        Mt[c * APAD + e0 + g]           = f2tf(h00);
        Mt[(c + 1) * APAD + e0 + g]     = f2tf(h01);
        Mt[c * APAD + e0 + g + 8]       = f2tf(h10);
        Mt[(c + 1) * APAD + e0 + g + 8] = f2tf(h11);
    }
    __syncwarp();

    float acc2[8][4];
#pragma unroll
    for (int i = 0; i < 8; i++)
#pragma unroll
        for (int j = 0; j < 4; j++) acc2[i][j] = 0.f;
    mma_chunk(Mt, Wt2, e0, lane, acc2);

    // stage output tile to SMEM (all warps must be done reading Mt first)
    __syncthreads();
#pragma unroll
    for (int nt = 0; nt < 8; nt++) {
        int c = nt * 8 + 2 * la3;
        *(float2*)(Ot + (e0 + g) * OPAD + c)     = make_float2(acc2[nt][0], acc2[nt][1]);
        *(float2*)(Ot + (e0 + g + 8) * OPAD + c) = make_float2(acc2[nt][2], acc2[nt][3]);
    }
    __syncthreads();

    // segmented reduction over sorted dsts: one red.v4 per (segment, 4-col chunk)
    {
        int cc = t & 15;        // 16 chunks of 4 cols
        int rg = t >> 4;        // 16 groups of 8 rows
        float4 sum = make_float4(0.f, 0.f, 0.f, 0.f);
        int cur = -1;
#pragma unroll
        for (int i = 0; i < 8; i++) {
            int r = rg * 8 + i;
            int dd = dsts[r];
            float4 v = *(const float4*)(Ot + r * OPAD + cc * 4);
            if (dd != cur) {
                if (cur >= 0) red4(d_acc + (size_t)cur * 64 + cc * 4, sum);
                cur = dd;
                sum = v;
            } else {
                sum.x += v.x; sum.y += v.y; sum.z += v.z; sum.w += v.w;
            }
        }
        if (cur >= 0) red4(d_acc + (size_t)cur * 64 + cc * 4, sum);
    }
}

// ---------------- finalize: mean (+residual) (+bn+relu), re-zero acc ----------------
__global__ void finalize_kernel(int mode, const float* __restrict__ bng, const float* __restrict__ bnb) {
    int i = blockIdx.x * blockDim.x + threadIdx.x;
    if (i >= NC) return;
    int n = i >> 6, c = i & 63;
    const int* cnt = (mode == 0) ? d_ic1 : d_ic2;
    float v = d_acc[i] / fmaxf((float)cnt[n], 1.f);
    d_acc[i] = 0.f;
    if (mode >= 2) v += d_cur[i];
    if (mode == 1 || mode == 2) v = fmaxf(v * (BNS * bng[c]) + bnb[c], 0.f);
    if (mode == 0) d_h[i] = v; else d_cur[i] = v;
}

// ---------------- heads ----------------
__global__ void heads_kernel(const float* __restrict__ fcW, const float* __restrict__ fcb,
                             const float* __restrict__ fcaW, const float* __restrict__ fcab,
                             const float* __restrict__ fcvW, const float* __restrict__ fcvb,
                             float* __restrict__ out)
{
    int n = blockIdx.x * blockDim.x + threadIdx.x;
    if (n >= NN) return;
    const float* f = d_cur + (size_t)n * 64;
    const float* g = d_gf  + (size_t)n * 64;
    bool even = (n & 1) == 0;
    const float* hw = even ? fcaW : fcvW;
    const float* hb = even ? fcab : fcvb;
    float o0 = fcb[0], o1 = fcb[1], h0 = hb[0], h1 = hb[1];
#pragma unroll 8
    for (int c = 0; c < 64; ++c) {
        float fv = f[c], gv = g[c];
        o0 += fv * fcW[2 * c];  o1 += fv * fcW[2 * c + 1];
        h0 += gv * hw[2 * c];   h1 += gv * hw[2 * c + 1];
    }
    out[2 * n] = o0; out[2 * n + 1] = o1;
    size_t off = even ? (size_t)2 * NN + (size_t)(n >> 1) * 2
                      : (size_t)2 * NN + (size_t)2 * HALFN + (size_t)(n >> 1) * 2;
    out[off] = h0; out[off + 1] = h1;
}

// ---------------- launch ----------------
extern "C" void kernel_launch(void* const* d_in, const int* in_sizes, int n_in,
                              void* d_out, int out_size) {
    const float* x    = (const float*)d_in[0];
    const int*   ei   = (const int*)d_in[1];
    const int*   dl   = (const int*)d_in[2];
    const int*   se   = (const int*)d_in[3];
    const float* W0a  = (const float*)d_in[5];
    const float* b0a  = (const float*)d_in[6];
    const float* W0v  = (const float*)d_in[7];
    const float* b0v  = (const float*)d_in[8];
    const float* bn0g = (const float*)d_in[9];
    const float* bn0b = (const float*)d_in[10];
    const float* ec1g = (const float*)d_in[11];
    const float* ec1b = (const float*)d_in[12];
    const float* ecW1 = (const float*)d_in[13];
    const float* ec2g = (const float*)d_in[14];
    const float* ec2b = (const float*)d_in[15];
    const float* ecW2 = (const float*)d_in[16];
    const float* bng  = (const float*)d_in[17];
    const float* bnb  = (const float*)d_in[18];
    const float* fcaW = (const float*)d_in[19];
    const float* fcab = (const float*)d_in[20];
    const float* fcvW = (const float*)d_in[21];
    const float* fcvb = (const float*)d_in[22];
    const float* fcW  = (const float*)d_in[23];
    const float* fcb  = (const float*)d_in[24];
    float* out = (float*)d_out;

    const int GEMM_SMEM = (64 * APAD + 64 * WPAD) * 4;                 // 51200
    const int MSG_SMEM  = (MT_WORDS + 2 * 64 * WPAD + 128) * 4;        // 72192
    cudaFuncSetAttribute(msg_kernel,    cudaFuncAttributeMaxDynamicSharedMemorySize, MSG_SMEM);
    cudaFuncSetAttribute(lin0_kernel,   cudaFuncAttributeMaxDynamicSharedMemorySize, GEMM_SMEM);
    cudaFuncSetAttribute(node_u_kernel, cudaFuncAttributeMaxDynamicSharedMemorySize, GEMM_SMEM);

    zero_kernel<<<1024, 256>>>();
    count_kernel<<<EE / 256, 256>>>(ei, dl, se);
    scan1_kernel<<<dim3(NBLK, 2), 1024>>>();
    scan2_kernel<<<1, 128>>>();
    scan3_kernel<<<dim3(NBLK, 2), 1024>>>();
    place_kernel<<<EE / 256, 256>>>(ei, dl, se);
    lin0_kernel<<<dim3((HALFN + 127) / 128, 2), 256, GEMM_SMEM>>>(x, W0a, b0a, W0v, b0v, bn0g, bn0b);

    int msgGrid = (EE + 127) / 128;
    int nuGrid  = (NN + 127) / 128;
    int finGrid = (NC + 255) / 256;
    for (int k = 0; k < 4; ++k) {
        const float* g1  = ec1g + k * 128;
        const float* b1  = ec1b + k * 128;
        const float* W1  = ecW1 + k * 8192;
        const float* g2  = ec2g + k * 64;
        const float* b2  = ec2b + k * 64;
        const float* W2  = ecW2 + k * 4096;
        int sel_cur = (k == 0) ? 0 : 2;

        node_u_kernel<<<nuGrid, 256, GEMM_SMEM>>>(sel_cur, g1, b1, W1);
        msg_kernel<<<msgGrid, 256, MSG_SMEM>>>(sel_cur, 0, g1 + 64, b1 + 64, W1 + 4096, g2, b2, W2);
        finalize_kernel<<<finGrid, 256>>>(0, nullptr, nullptr);

        node_u_kernel<<<nuGrid, 256, GEMM_SMEM>>>(1, g1, b1, W1);
        msg_kernel<<<msgGrid, 256, MSG_SMEM>>>(1, 1, g1 + 64, b1 + 64, W1 + 4096, g2, b2, W2);
        int mode = (k == 0) ? 1 : (k == 3 ? 3 : 2);
        const float* gB = (k < 3) ? bng + k * 64 : nullptr;
        const float* bB = (k < 3) ? bnb + k * 64 : nullptr;
        finalize_kernel<<<finGrid, 256>>>(mode, gB, bB);
    }
    heads_kernel<<<(NN + 255) / 256, 256>>>(fcW, fcb, fcaW, fcab, fcvW, fcvb, out);
}